// round 10
// baseline (speedup 1.0000x reference)
#include <cuda_runtime.h>
#include <math.h>

#define NB    32
#define NPG   4096
#define NTOT  (NB*NPG)      // 131072 nodes
#define FIN   64
#define CD    128
#define KD    32
#define JD    40
#define EPSV  1e-5f
#define TPB   256

typedef unsigned long long u64;

__device__ __forceinline__ u64 PK2(float lo, float hi) {
    u64 r; asm("mov.b64 %0, {%1,%2};" : "=l"(r) : "f"(lo), "f"(hi)); return r;
}
__device__ __forceinline__ u64 SPLAT(float v) {
    u64 r; asm("mov.b64 %0, {%1,%1};" : "=l"(r) : "f"(v)); return r;
}
__device__ __forceinline__ void FMA2(u64& d, u64 a, u64 b) {
    asm("fma.rn.f32x2 %0, %1, %2, %0;" : "+l"(d) : "l"(a), "l"(b));
}
__device__ __forceinline__ float2 UPK(u64 v) {
    float lo, hi; asm("mov.b64 {%0,%1}, %2;" : "=f"(lo), "=f"(hi) : "l"(v));
    return make_float2(lo, hi);
}
__device__ __forceinline__ float HSUM(u64 v) { float2 p = UPK(v); return p.x + p.y; }

// ---------------- scratch (device globals: no allocs allowed) ----------------
__device__ float  g_t [NTOT*CD];     // t = nf@W^T+b, later in-place gated x
__device__ float  g_P [NTOT*JD];     // raw I per layer
__device__ float  g_ty[NB*JD*CD];    // frag pre-LN
__device__ float  g_yp[NB*JD*KD];    // y_p (raw)
__device__ float  g_G [NB*KD*KD];    // y_p^T y_p per graph
__device__ double g_red[4];          // node sum/sumsq, frag sum/sumsq
__device__ float  g_M[2*NB*JD];      // per-layer column max (I>=0 so init 0 ok)
__device__ float  g_S[2*NB*JD];      // per-layer column sum-exp

__device__ __forceinline__ void node_ln(float& mean, float& rstd) {
    double ne = (double)NTOT * CD;
    double m  = g_red[0] / ne;
    double v  = g_red[1] / ne - m*m;
    mean = (float)m;
    rstd = (float)(1.0 / sqrt(v + (double)EPSV));
}

// ---------------------------------------------------------------------------
__global__ void k_zero() {
    int t = blockIdx.x*blockDim.x + threadIdx.x;
    if (t < 4) g_red[t] = 0.0;
    if (t < 2*NB*JD) { g_M[t] = 0.f; g_S[t] = 0.f; }
}

// out[row][c] = sum_d in[row][d]*W[c][d] + b[c]; 128 rows x 128 cols per block.
// Thread tile 8 rows x 4 strided pairs: 8 bcast + 4 LDS64 per k vs 32 FMA2 (balanced).
__global__ void k_in_gemm(const float* __restrict__ in, const float* __restrict__ W,
                          const float* __restrict__ bias, int which)
{
    extern __shared__ float sm[];
    float* As = sm;               // [128][68]
    float* Ws = As + 128*68;      // [64][132] W^T, k-major
    float* bs = Ws + 64*132;      // [128]
    float* r1 = bs + 128;         // [8]
    float* r2 = r1 + 8;           // [8]
    float* outg = which ? g_ty : g_t;
    const int slot = which * 2;
    const int t = threadIdx.x;
    const int base = blockIdx.x * 128;

    #pragma unroll
    for (int i = 0; i < 8; i++) {                 // A tile: 128x64 floats
        int f = t + i*TPB;
        int r = f >> 4, cq = f & 15;
        float4 v = reinterpret_cast<const float4*>(in)[(base + r)*(FIN/4) + cq];
        *reinterpret_cast<float4*>(&As[r*68 + cq*4]) = v;
    }
    #pragma unroll
    for (int i = 0; i < 8; i++) {                 // W [128][64] -> Ws[k][c]
        int f = t + i*TPB;
        int c = f >> 4, kq = f & 15;
        float4 v = reinterpret_cast<const float4*>(W)[c*(FIN/4) + kq];
        Ws[(kq*4+0)*132 + c] = v.x;
        Ws[(kq*4+1)*132 + c] = v.y;
        Ws[(kq*4+2)*132 + c] = v.z;
        Ws[(kq*4+3)*132 + c] = v.w;
    }
    if (t < CD) bs[t] = bias[t];
    __syncthreads();

    const int rg = t >> 4, cg = t & 15;           // 8 rows x 4 strided pairs
    u64 acc[8][4] = {};

    #pragma unroll 4
    for (int k = 0; k < 64; k++) {
        u64 av[8], bv[4];
        #pragma unroll
        for (int m = 0; m < 8; m++) av[m] = SPLAT(As[(rg*8+m)*68 + k]);
        #pragma unroll
        for (int u = 0; u < 4; u++)
            bv[u] = *reinterpret_cast<const u64*>(&Ws[k*132 + cg*2 + 32*u]);
        #pragma unroll
        for (int m = 0; m < 8; m++)
            #pragma unroll
            for (int u = 0; u < 4; u++) FMA2(acc[m][u], av[m], bv[u]);
    }

    float s1 = 0.f, s2 = 0.f;
    #pragma unroll
    for (int m = 0; m < 8; m++) {
        int row = base + rg*8 + m;
        #pragma unroll
        for (int u = 0; u < 4; u++) {
            float2 p = UPK(acc[m][u]);
            float o0 = p.x + bs[cg*2 + 32*u];
            float o1 = p.y + bs[cg*2 + 32*u + 1];
            s1 += o0 + o1;
            s2 = fmaf(o0, o0, fmaf(o1, o1, s2));
            *reinterpret_cast<float2*>(&outg[row*CD + cg*2 + 32*u]) = make_float2(o0, o1);
        }
    }
    #pragma unroll
    for (int off = 16; off; off >>= 1) {
        s1 += __shfl_xor_sync(0xffffffffu, s1, off);
        s2 += __shfl_xor_sync(0xffffffffu, s2, off);
    }
    if ((t & 31) == 0) { r1[t>>5] = s1; r2[t>>5] = s2; }
    __syncthreads();
    if (t == 0) {
        float a = 0.f, b = 0.f;
        #pragma unroll
        for (int w = 0; w < 8; w++) { a += r1[w]; b += r2[w]; }
        atomicAdd(&g_red[slot],   (double)a);
        atomicAdd(&g_red[slot+1], (double)b);
    }
}

// per graph: y_p = relu(q * relu(LN(ty) @ V)), G = y_p^T y_p
__global__ void k_yp(const float* __restrict__ V, const float* __restrict__ q)
{
    extern __shared__ float sm[];
    float* ysn = sm;              // [40][128]
    float* Vs  = ysn + JD*CD;     // [128][32]
    float* yps = Vs + CD*KD;      // [40][32]
    float* qs  = yps + JD*KD;     // [32]
    const int t = threadIdx.x, b = blockIdx.x;
    double nf = (double)NB * JD * CD;
    double dm = g_red[2] / nf;
    double dv = g_red[3] / nf - dm*dm;
    const float mf = (float)dm;
    const float rf = (float)(1.0 / sqrt(dv + (double)EPSV));
    for (int i = t; i < JD*CD; i += TPB) ysn[i] = (g_ty[b*JD*CD + i] - mf) * rf;
    for (int i = t; i < CD*KD; i += TPB) Vs[i] = V[i];
    if (t < KD) qs[t] = q[t];
    __syncthreads();
    #pragma unroll
    for (int i = 0; i < 5; i++) {
        int o = t + i*TPB;
        int j = o >> 5, k = o & 31;
        float acc = 0.f;
        #pragma unroll 16
        for (int d = 0; d < CD; d++) acc = fmaf(ysn[j*CD+d], Vs[d*KD+k], acc);
        float r = fmaxf(qs[k] * fmaxf(acc, 0.f), 0.f);
        yps[j*KD+k] = r;
        g_yp[b*JD*KD + o] = r;
    }
    __syncthreads();
    #pragma unroll
    for (int i = 0; i < 4; i++) {
        int o = t + i*TPB;
        int k1 = o >> 5, k2 = o & 31;
        float acc = 0.f;
        #pragma unroll
        for (int j = 0; j < JD; j++) acc = fmaf(yps[j*KD+k1], yps[j*KD+k2], acc);
        g_G[b*KD*KD + o] = acc;
    }
}

// 128 nodes/block: x_p = relu(x@U); I = x_p @ y_p^T; write I; shfl-max -> atomicMax
__global__ void k_xp_I(const float* __restrict__ U, int layer)
{
    extern __shared__ float sm[];
    float* Xs  = sm;               // [128][132]  (Is [128][41] overlays after phase1)
    float* Is  = sm;
    float* Ust = sm + 128*132;     // [32][134]  U transposed (k-major over c)
    float* Xps = Ust + 32*134;     // [128][34]
    float* Yps = Xps + 128*34;     // [40][32]
    const int t = threadIdx.x;
    const int b = blockIdx.x >> 5, tile = blockIdx.x & 31;
    const int base = b*NPG + tile*128;
    float mean = 0.f, rstd = 1.f;
    if (layer == 0) node_ln(mean, rstd);

    #pragma unroll
    for (int i = 0; i < 16; i++) {
        int f = t + i*TPB;
        int r = f >> 5, cq = f & 31;
        float4 v = reinterpret_cast<const float4*>(g_t)[(base + r)*(CD/4) + cq];
        v.x = (v.x-mean)*rstd; v.y = (v.y-mean)*rstd;
        v.z = (v.z-mean)*rstd; v.w = (v.w-mean)*rstd;
        *reinterpret_cast<float4*>(&Xs[r*132 + cq*4]) = v;
    }
    #pragma unroll
    for (int i = 0; i < 16; i++) {                // U [128][32] -> Ust[k][c]
        int f = t + i*TPB;
        int c = f >> 5, k = f & 31;
        Ust[k*134 + c] = U[f];
    }
    for (int i = t; i < JD*KD; i += TPB) Yps[i] = g_yp[b*JD*KD + i];
    __syncthreads();

    { // phase 1: Xp = relu(X@U), 4 rows x 4 cols, k-packed over c
        const int rg = t >> 3, cg = t & 7;
        u64 acc[4][4] = {};
        #pragma unroll 4
        for (int c2 = 0; c2 < 64; c2++) {
            u64 a2[4], b2[4];
            #pragma unroll
            for (int m = 0; m < 4; m++)
                a2[m] = *reinterpret_cast<const u64*>(&Xs[(rg*4+m)*132 + 2*c2]);
            #pragma unroll
            for (int d = 0; d < 4; d++)
                b2[d] = *reinterpret_cast<const u64*>(&Ust[(cg*4+d)*134 + 2*c2]);
            #pragma unroll
            for (int m = 0; m < 4; m++)
                #pragma unroll
                for (int d = 0; d < 4; d++) FMA2(acc[m][d], a2[m], b2[d]);
        }
        __syncthreads();   // Xs dead; Is may be written below
        #pragma unroll
        for (int m = 0; m < 4; m++)
            #pragma unroll
            for (int d = 0; d < 4; d++)
                Xps[(rg*4+m)*34 + cg*4 + d] = fmaxf(HSUM(acc[m][d]), 0.f);
    }
    __syncthreads();

    { // phase 2: I = Xp @ Yps^T; warp-uniform j -> Yps loads are broadcasts.
      // thread = 4 rows x 5 j;  jg = t>>5 (one warp per j-group), rr = t&31
        const int jg = t >> 5, rr = t & 31;
        u64 acc2[4][5] = {};
        #pragma unroll
        for (int kc = 0; kc < 4; kc++) {
            u64 xp[4][4];
            #pragma unroll
            for (int m = 0; m < 4; m++)
                #pragma unroll
                for (int p = 0; p < 4; p++)
                    xp[m][p] = *reinterpret_cast<const u64*>(&Xps[(rr*4+m)*34 + kc*8 + 2*p]);
            #pragma unroll
            for (int jj = 0; jj < 5; jj++) {
                int j = jg*5 + jj;
                u64 yv[4];
                #pragma unroll
                for (int p = 0; p < 4; p++)
                    yv[p] = *reinterpret_cast<const u64*>(&Yps[j*32 + kc*8 + 2*p]);
                #pragma unroll
                for (int m = 0; m < 4; m++)
                    #pragma unroll
                    for (int p = 0; p < 4; p++) FMA2(acc2[m][jj], xp[m][p], yv[p]);
            }
        }
        #pragma unroll
        for (int jj = 0; jj < 5; jj++) {
            float s[4], v;
            #pragma unroll
            for (int m = 0; m < 4; m++) {
                s[m] = HSUM(acc2[m][jj]);
                Is[(rr*4+m)*41 + jg*5 + jj] = s[m];
            }
            v = fmaxf(fmaxf(s[0], s[1]), fmaxf(s[2], s[3]));
            #pragma unroll
            for (int off = 16; off; off >>= 1)
                v = fmaxf(v, __shfl_xor_sync(0xffffffffu, v, off));
            if (rr == 0)
                atomicMax((int*)(g_M + layer*NB*JD + b*JD + jg*5 + jj), __float_as_int(v));
        }
    }
    __syncthreads();

    float* gP = g_P + (long)base * JD;
    for (int o = t; o < 128*JD; o += TPB) gP[o] = Is[(o/JD)*41 + (o%JD)];
}

// accumulate column sum of exp(I-M); read-only on g_P
__global__ void k_sumexp(int layer)
{
    __shared__ float Ms[JD], sj[JD];
    const int t = threadIdx.x;
    const int b = blockIdx.x >> 5, chunk = blockIdx.x & 31;    // 128 nodes/block
    const long base = ((long)b*NPG + chunk*128) * JD;
    if (t < JD) { Ms[t] = g_M[layer*NB*JD + b*JD + t]; sj[t] = 0.f; }
    __syncthreads();
    float loc[5] = {0,0,0,0,0};
    #pragma unroll
    for (int i = 0; i < 20; i++) {                // 128*40 / 256
        int o = t + i*TPB;
        int j = o % JD;
        loc[j >> 3] += __expf(g_P[base + o] - Ms[j]);
    }
    const int jc = t & 7;
    #pragma unroll
    for (int i = 0; i < 5; i++) atomicAdd(&sj[i*8 + jc], loc[i]);
    __syncthreads();
    if (t < JD) atomicAdd(&g_S[layer*NB*JD + b*JD + t], sj[t]);
}

// E = exp(I-M); H = relu(E @ (y_p/S)); hC = H@V^T (staged in smem); gate; update x
__global__ void k_h_gate(const float* __restrict__ V, const float* __restrict__ gW,
                         const float* __restrict__ gb, int layer)
{
    extern __shared__ float sm[];
    float* Es   = sm;                 // [128][41]   (hCs [128][132] overlays)
    float* hCs  = sm;
    float* Yps2 = sm + 128*132;       // [40][32]  y_p/S
    float* Hs   = Yps2 + JD*KD;       // [128][34]
    float* Vst  = Hs + 128*34;        // [32][132] (k-major V^T)
    float* Ms   = Vst + KD*132;       // [40]
    float* invS = Ms + JD;            // [40]
    float* gws  = invS + JD;          // [256]
    const int t = threadIdx.x;
    const int b = blockIdx.x >> 5, tile = blockIdx.x & 31;
    const int base = b*NPG + tile*128;
    float mean = 0.f, rstd = 1.f;
    if (layer == 0) node_ln(mean, rstd);
    const float gb0 = gb[0];

    if (t < JD) {
        Ms[t]   = g_M[layer*NB*JD + b*JD + t];
        invS[t] = 1.f / g_S[layer*NB*JD + b*JD + t];
    }
    gws[t] = gW[t];
    __syncthreads();
    for (int i = t; i < JD*KD; i += TPB) Yps2[i] = g_yp[b*JD*KD + i] * invS[i >> 5];
    #pragma unroll
    for (int i = 0; i < 4; i++) {                  // V [128][32] -> Vst[k][c]
        int f = t + i*TPB;
        int c = f >> 3, kq = f & 7;
        float4 v = reinterpret_cast<const float4*>(V)[c*(KD/4) + kq];
        Vst[(kq*4+0)*132 + c] = v.x;
        Vst[(kq*4+1)*132 + c] = v.y;
        Vst[(kq*4+2)*132 + c] = v.z;
        Vst[(kq*4+3)*132 + c] = v.w;
    }
    #pragma unroll
    for (int i = 0; i < 20; i++) {
        int o = t + i*TPB;
        int r = o / JD, j = o - r*JD;
        Es[r*41 + j] = __expf(g_P[(long)base*JD + o] - Ms[j]);
    }
    __syncthreads();

    const int rg = t >> 4, cg = t & 15;
    { // phase 1: H[128][32] = relu(E @ Yps2), 8 rows x 1 pair
        u64 acc[8] = {};
        #pragma unroll 8
        for (int j = 0; j < JD; j++) {
            u64 b2 = *reinterpret_cast<const u64*>(&Yps2[j*32 + cg*2]);
            #pragma unroll
            for (int m = 0; m < 8; m++)
                FMA2(acc[m], SPLAT(Es[(rg*8+m)*41 + j]), b2);
        }
        __syncthreads();   // Es dead after this; hCs writes come later
        #pragma unroll
        for (int m = 0; m < 8; m++) {
            float2 p = UPK(acc[m]);
            *reinterpret_cast<u64*>(&Hs[(rg*8+m)*34 + cg*2]) =
                PK2(fmaxf(p.x, 0.f), fmaxf(p.y, 0.f));
        }
    }
    __syncthreads();

    { // phase 2: hC[128][128] = H @ V^T, 8 rows x 4 strided pairs -> smem
        u64 hc[8][4] = {};
        #pragma unroll 4
        for (int k = 0; k < KD; k++) {
            u64 av[8], bv[4];
            #pragma unroll
            for (int m = 0; m < 8; m++) av[m] = SPLAT(Hs[(rg*8+m)*34 + k]);
            #pragma unroll
            for (int u = 0; u < 4; u++)
                bv[u] = *reinterpret_cast<const u64*>(&Vst[k*132 + cg*2 + 32*u]);
            #pragma unroll
            for (int m = 0; m < 8; m++)
                #pragma unroll
                for (int u = 0; u < 4; u++) FMA2(hc[m][u], av[m], bv[u]);
        }
        #pragma unroll
        for (int m = 0; m < 8; m++)
            #pragma unroll
            for (int u = 0; u < 4; u++) {
                float2 p = UPK(hc[m][u]);
                *reinterpret_cast<float2*>(&hCs[(rg*8+m)*132 + cg*2 + 32*u]) = p;
            }
    }
    __syncthreads();

    { // epilogue: 2 threads per row; gate dot + shfl + in-place x update
        const int row = t >> 1, half = t & 1;
        const int cb = half * 64;
        const float4* xr = reinterpret_cast<const float4*>(&g_t[(long)(base+row)*CD + cb]);
        float4*       xw = reinterpret_cast<float4*>(&g_t[(long)(base+row)*CD + cb]);
        float p = 0.f;
        #pragma unroll
        for (int c4 = 0; c4 < 16; c4++) {
            float4 x = xr[c4];
            float4 h = *reinterpret_cast<const float4*>(&hCs[row*132 + cb + c4*4]);
            float4 g1 = *reinterpret_cast<const float4*>(&gws[cb + c4*4]);
            float4 g2 = *reinterpret_cast<const float4*>(&gws[CD + cb + c4*4]);
            float x0=(x.x-mean)*rstd, x1=(x.y-mean)*rstd, x2=(x.z-mean)*rstd, x3=(x.w-mean)*rstd;
            p = fmaf(x0,g1.x, fmaf(x1,g1.y, fmaf(x2,g1.z, fmaf(x3,g1.w, p))));
            p = fmaf(h.x,g2.x, fmaf(h.y,g2.y, fmaf(h.z,g2.z, fmaf(h.w,g2.w, p))));
        }
        p += __shfl_xor_sync(0xffffffffu, p, 1);
        float z = 1.f / (1.f + __expf(-(p + gb0)));
        #pragma unroll
        for (int c4 = 0; c4 < 16; c4++) {
            float4 x = xr[c4];
            float4 h = *reinterpret_cast<const float4*>(&hCs[row*132 + cb + c4*4]);
            float x0=(x.x-mean)*rstd, x1=(x.y-mean)*rstd, x2=(x.z-mean)*rstd, x3=(x.w-mean)*rstd;
            float4 o;
            o.x = fmaf(z, h.x - x0, x0);
            o.y = fmaf(z, h.y - x1, x1);
            o.z = fmaf(z, h.z - x2, x2);
            o.w = fmaf(z, h.w - x3, x3);
            xw[c4] = o;
        }
    }
}

// x_p = relu(x@U); out = sigmoid(x_p . (x_p @ G))
__global__ void k_final(const float* __restrict__ U, float* __restrict__ out)
{
    extern __shared__ float sm[];
    float* Xs  = sm;               // [128][132]
    float* Ust = sm + 128*132;     // [32][134]
    float* Xps = Ust + 32*134;     // [128][34]
    float* Gs  = Xps + 128*34;     // [32][32]
    const int t = threadIdx.x;
    const int b = blockIdx.x >> 5, tile = blockIdx.x & 31;
    const int base = b*NPG + tile*128;

    #pragma unroll
    for (int i = 0; i < 16; i++) {
        int f = t + i*TPB;
        int r = f >> 5, cq = f & 31;
        float4 v = reinterpret_cast<const float4*>(g_t)[(base + r)*(CD/4) + cq];
        *reinterpret_cast<float4*>(&Xs[r*132 + cq*4]) = v;
    }
    #pragma unroll
    for (int i = 0; i < 16; i++) {
        int f = t + i*TPB;
        int c = f >> 5, k = f & 31;
        Ust[k*134 + c] = U[f];
    }
    for (int i = t; i < KD*KD; i += TPB) Gs[i] = g_G[b*KD*KD + i];
    __syncthreads();

    { // phase 1: Xp = relu(X@U), 4r x 4c k-packed
        const int rg = t >> 3, cg = t & 7;
        u64 acc[4][4] = {};
        #pragma unroll 4
        for (int c2 = 0; c2 < 64; c2++) {
            u64 a2[4], b2[4];
            #pragma unroll
            for (int m = 0; m < 4; m++)
                a2[m] = *reinterpret_cast<const u64*>(&Xs[(rg*4+m)*132 + 2*c2]);
            #pragma unroll
            for (int d = 0; d < 4; d++)
                b2[d] = *reinterpret_cast<const u64*>(&Ust[(cg*4+d)*134 + 2*c2]);
            #pragma unroll
            for (int m = 0; m < 4; m++)
                #pragma unroll
                for (int d = 0; d < 4; d++) FMA2(acc[m][d], a2[m], b2[d]);
        }
        #pragma unroll
        for (int m = 0; m < 4; m++)
            #pragma unroll
            for (int d = 0; d < 4; d++)
                Xps[(rg*4+m)*34 + cg*4 + d] = fmaxf(HSUM(acc[m][d]), 0.f);
    }
    __syncthreads();

    { // phase 2: tvec = Xp@G (8 rows x 1 pair), dot with Xp, reduce over 16 lanes
        const int rg = t >> 4, cg = t & 15;
        u64 acc[8] = {};
        #pragma unroll
        for (int k = 0; k < KD; k++) {
            u64 b2 = *reinterpret_cast<const u64*>(&Gs[k*32 + cg*2]);
            #pragma unroll
            for (int m = 0; m < 8; m++)
                FMA2(acc[m], SPLAT(Xps[(rg*8+m)*34 + k]), b2);
        }
        float part[8];
        #pragma unroll
        for (int m = 0; m < 8; m++) {
            float2 p = UPK(acc[m]);
            part[m] = p.x * Xps[(rg*8+m)*34 + cg*2]
                    + p.y * Xps[(rg*8+m)*34 + cg*2 + 1];
        }
        #pragma unroll
        for (int off = 8; off; off >>= 1)
            #pragma unroll
            for (int m = 0; m < 8; m++)
                part[m] += __shfl_xor_sync(0xffffffffu, part[m], off);
        if (cg == 0) {
            #pragma unroll
            for (int m = 0; m < 8; m++)
                out[base + rg*8 + m] = 1.f / (1.f + __expf(-part[m]));
        }
    }
}

// ---------------------------------------------------------------------------
extern "C" void kernel_launch(void* const* d_in, const int* in_sizes, int n_in,
                              void* d_out, int out_size)
{
    (void)in_sizes; (void)n_in; (void)out_size;
    const float* nf   = (const float*)d_in[0];
    const float* frag = (const float*)d_in[1];
    const float* Wi   = (const float*)d_in[2];
    const float* bi   = (const float*)d_in[3];
    const float* U    = (const float*)d_in[4];
    const float* V    = (const float*)d_in[5];
    const float* q    = (const float*)d_in[6];
    const float* gW   = (const float*)d_in[7];
    const float* gb   = (const float*)d_in[8];
    float* out = (float*)d_out;

    const int SM_GEMM = (128*68 + 64*132 + 128 + 16) * 4;                    // 69184
    const int SM_YP   = (JD*CD + CD*KD + JD*KD + KD) * 4;                    // 42112
    const int SM_XPI  = (128*132 + 32*134 + 128*34 + JD*KD) * 4;             // 107264
    const int SM_HG   = (128*132 + JD*KD + 128*34 + KD*132 + 2*JD + 256) * 4;// 108544
    const int SM_FIN  = (128*132 + 32*134 + 128*34 + KD*KD) * 4;             // 106240

    cudaFuncSetAttribute((const void*)k_in_gemm, cudaFuncAttributeMaxDynamicSharedMemorySize, SM_GEMM);
    cudaFuncSetAttribute((const void*)k_yp,      cudaFuncAttributeMaxDynamicSharedMemorySize, SM_YP);
    cudaFuncSetAttribute((const void*)k_xp_I,    cudaFuncAttributeMaxDynamicSharedMemorySize, SM_XPI);
    cudaFuncSetAttribute((const void*)k_h_gate,  cudaFuncAttributeMaxDynamicSharedMemorySize, SM_HG);
    cudaFuncSetAttribute((const void*)k_final,   cudaFuncAttributeMaxDynamicSharedMemorySize, SM_FIN);

    k_zero<<<10, TPB>>>();
    k_in_gemm<<<NTOT/128, TPB, SM_GEMM>>>(nf, Wi, bi, 0);
    k_in_gemm<<<NB*JD/128, TPB, SM_GEMM>>>(frag, Wi, bi, 1);
    k_yp<<<NB, TPB, SM_YP>>>(V, q);

    for (int l = 0; l < 2; l++) {
        k_xp_I  <<<NTOT/128, TPB, SM_XPI>>>(U, l);
        k_sumexp<<<NTOT/128, TPB>>>(l);
        k_h_gate<<<NTOT/128, TPB, SM_HG>>>(V, gW, gb, l);
    }
    k_final<<<NTOT/128, TPB, SM_FIN>>>(U, out);
}

// round 11
// speedup vs baseline: 1.1539x; 1.1539x over previous
#include <cuda_runtime.h>
#include <math.h>

#define NB    32
#define NPG   4096
#define NTOT  (NB*NPG)      // 131072 nodes
#define FIN   64
#define CD    128
#define KD    32
#define JD    40
#define EPSV  1e-5f
#define TPB   256

typedef unsigned long long u64;

__device__ __forceinline__ u64 PK2(float lo, float hi) {
    u64 r; asm("mov.b64 %0, {%1,%2};" : "=l"(r) : "f"(lo), "f"(hi)); return r;
}
__device__ __forceinline__ u64 SPLAT(float v) {
    u64 r; asm("mov.b64 %0, {%1,%1};" : "=l"(r) : "f"(v)); return r;
}
__device__ __forceinline__ void FMA2(u64& d, u64 a, u64 b) {
    asm("fma.rn.f32x2 %0, %1, %2, %0;" : "+l"(d) : "l"(a), "l"(b));
}
__device__ __forceinline__ float2 UPK(u64 v) {
    float lo, hi; asm("mov.b64 {%0,%1}, %2;" : "=f"(lo), "=f"(hi) : "l"(v));
    return make_float2(lo, hi);
}

// ---------------- scratch (device globals: no allocs allowed) ----------------
__device__ float  g_t [NTOT*CD];     // t = nf@W^T+b, later in-place gated x
__device__ float  g_P [NTOT*JD];     // raw I per layer
__device__ float  g_ty[NB*JD*CD];    // frag pre-LN
__device__ float  g_yp[NB*JD*KD];    // y_p (raw)
__device__ float  g_G [NB*KD*KD];    // y_p^T y_p per graph
__device__ double g_red[4];          // node sum/sumsq, frag sum/sumsq
__device__ float  g_M[2*NB*JD];      // per-layer column max (I>=0 so init 0 ok)
__device__ float  g_S[2*NB*JD];      // per-layer column sum-exp

__device__ __forceinline__ void node_ln(float& mean, float& rstd) {
    double ne = (double)NTOT * CD;
    double m  = g_red[0] / ne;
    double v  = g_red[1] / ne - m*m;
    mean = (float)m;
    rstd = (float)(1.0 / sqrt(v + (double)EPSV));
}
__device__ __forceinline__ void frag_ln(float& mean, float& rstd) {
    double nf = (double)NB * JD * CD;
    double m  = g_red[2] / nf;
    double v  = g_red[3] / nf - m*m;
    mean = (float)m;
    rstd = (float)(1.0 / sqrt(v + (double)EPSV));
}

// ---------------------------------------------------------------------------
__global__ void k_zero() {
    int t = blockIdx.x*blockDim.x + threadIdx.x;
    if (t < 4) g_red[t] = 0.0;
    if (t < 2*NB*JD) { g_M[t] = 0.f; g_S[t] = 0.f; }
}

// out[row][c] = sum_d in[row][d]*W[c][d] + b[c]; 64 rows x 128 cols per block.
// f32x2: strided column pairs (2cg + 32u) -> conflict-free LDS64 on Ws.
__global__ void k_in_gemm(const float* __restrict__ in, const float* __restrict__ W,
                          const float* __restrict__ bias, int which)
{
    extern __shared__ float sm[];
    float* As = sm;              // [64][68]  input tile
    float* Ws = As + 64*68;      // [64][132] W^T, k-major
    float* bs = Ws + 64*132;     // [128]
    float* r1 = bs + 128;        // [8]
    float* r2 = r1 + 8;          // [8]
    float* outg = which ? g_ty : g_t;
    const int slot = which * 2;
    const int t = threadIdx.x;
    const int base = blockIdx.x * 64;

    #pragma unroll
    for (int i = 0; i < 4; i++) {                 // A tile: 64x64 floats
        int f = t + i*TPB;
        int r = f >> 4, cq = f & 15;
        float4 v = reinterpret_cast<const float4*>(in)[(base + r)*(FIN/4) + cq];
        *reinterpret_cast<float4*>(&As[r*68 + cq*4]) = v;
    }
    #pragma unroll
    for (int i = 0; i < 8; i++) {                 // W [128][64] -> Ws[k][c]
        int f = t + i*TPB;
        int c = f >> 4, kq = f & 15;
        float4 v = reinterpret_cast<const float4*>(W)[c*(FIN/4) + kq];
        Ws[(kq*4+0)*132 + c] = v.x;
        Ws[(kq*4+1)*132 + c] = v.y;
        Ws[(kq*4+2)*132 + c] = v.z;
        Ws[(kq*4+3)*132 + c] = v.w;
    }
    if (t < CD) bs[t] = bias[t];
    __syncthreads();

    const int rg = t >> 4, cg = t & 15;           // 4 rows x 4 strided pairs
    u64 acc[4][4] = {};

    #pragma unroll 4
    for (int k = 0; k < 64; k++) {
        u64 av[4], bv[4];
        #pragma unroll
        for (int m = 0; m < 4; m++) av[m] = SPLAT(As[(rg*4+m)*68 + k]);
        #pragma unroll
        for (int u = 0; u < 4; u++)
            bv[u] = *reinterpret_cast<const u64*>(&Ws[k*132 + cg*2 + 32*u]);
        #pragma unroll
        for (int m = 0; m < 4; m++)
            #pragma unroll
            for (int u = 0; u < 4; u++) FMA2(acc[m][u], av[m], bv[u]);
    }

    float s1 = 0.f, s2 = 0.f;
    #pragma unroll
    for (int m = 0; m < 4; m++) {
        int row = base + rg*4 + m;
        #pragma unroll
        for (int u = 0; u < 4; u++) {
            float2 p = UPK(acc[m][u]);
            float o0 = p.x + bs[cg*2 + 32*u];
            float o1 = p.y + bs[cg*2 + 32*u + 1];
            s1 += o0 + o1;
            s2 = fmaf(o0, o0, fmaf(o1, o1, s2));
            *reinterpret_cast<float2*>(&outg[row*CD + cg*2 + 32*u]) = make_float2(o0, o1);
        }
    }
    #pragma unroll
    for (int off = 16; off; off >>= 1) {
        s1 += __shfl_xor_sync(0xffffffffu, s1, off);
        s2 += __shfl_xor_sync(0xffffffffu, s2, off);
    }
    if ((t & 31) == 0) { r1[t>>5] = s1; r2[t>>5] = s2; }
    __syncthreads();
    if (t == 0) {
        float a = 0.f, b = 0.f;
        #pragma unroll
        for (int w = 0; w < 8; w++) { a += r1[w]; b += r2[w]; }
        atomicAdd(&g_red[slot],   (double)a);
        atomicAdd(&g_red[slot+1], (double)b);
    }
}

// y_p = relu(q * relu(LN(ty) @ V)); grid NB*5, each block = 8 j rows of one graph.
__global__ void k_yp(const float* __restrict__ V, const float* __restrict__ q)
{
    __shared__ float ysn[8*132];
    __shared__ float Vs[CD*KD];
    __shared__ float qs[KD];
    const int t = threadIdx.x;
    const int b = blockIdx.x / 5, jg = blockIdx.x % 5;
    float mf, rf; frag_ln(mf, rf);

    #pragma unroll
    for (int i = 0; i < 4; i++) {                  // 8 rows x 128 = 1024 floats
        int f = t + i*TPB;
        int r = f >> 7, c = f & 127;
        ysn[r*132 + c] = (g_ty[(b*JD + jg*8 + r)*CD + c] - mf) * rf;
    }
    #pragma unroll
    for (int i = 0; i < 16; i++) Vs[t + i*TPB] = V[t + i*TPB];
    if (t < KD) qs[t] = q[t];
    __syncthreads();

    const int j = t >> 5, k = t & 31;              // one output per thread
    float a0 = 0.f, a1 = 0.f, a2 = 0.f, a3 = 0.f;
    #pragma unroll
    for (int d = 0; d < CD; d += 4) {
        a0 = fmaf(ysn[j*132 + d    ], Vs[(d    )*KD + k], a0);
        a1 = fmaf(ysn[j*132 + d + 1], Vs[(d + 1)*KD + k], a1);
        a2 = fmaf(ysn[j*132 + d + 2], Vs[(d + 2)*KD + k], a2);
        a3 = fmaf(ysn[j*132 + d + 3], Vs[(d + 3)*KD + k], a3);
    }
    float acc = (a0 + a1) + (a2 + a3);
    g_yp[b*JD*KD + (jg*8 + j)*KD + k] = fmaxf(qs[k] * fmaxf(acc, 0.f), 0.f);
}

// G = y_p^T y_p per graph; grid NB
__global__ void k_G()
{
    __shared__ float yps[JD*KD];
    const int t = threadIdx.x, b = blockIdx.x;
    for (int i = t; i < JD*KD; i += TPB) yps[i] = g_yp[b*JD*KD + i];
    __syncthreads();
    #pragma unroll
    for (int i = 0; i < 4; i++) {
        int o = t + i*TPB;
        int k1 = o >> 5, k2 = o & 31;
        float acc = 0.f;
        #pragma unroll
        for (int j = 0; j < JD; j++) acc = fmaf(yps[j*KD+k1], yps[j*KD+k2], acc);
        g_G[b*KD*KD + o] = acc;
    }
}

// 64 nodes/block: x_p = relu(x@U); I = x_p @ y_p^T; write I; atomicMax column max
__global__ void k_xp_I(const float* __restrict__ U, int layer)
{
    extern __shared__ float sm[];
    float* Xs  = sm;               // [64][132]
    float* Ust = Xs + 64*132;      // [32][134]  U transposed, k-major over c
    float* Xps = Ust + 32*134;     // [64][34]
    float* Yps = Xps + 64*34;      // [40][32]
    float* Is  = Yps + JD*KD;      // [64][41]
    const int t = threadIdx.x;
    const int b = blockIdx.x >> 6, tile = blockIdx.x & 63;
    const int base = b*NPG + tile*64;
    float mean = 0.f, rstd = 1.f;
    if (layer == 0) node_ln(mean, rstd);

    #pragma unroll
    for (int i = 0; i < 8; i++) {
        int f = t + i*TPB;
        int r = f >> 5, cq = f & 31;
        float4 v = reinterpret_cast<const float4*>(g_t)[(base + r)*(CD/4) + cq];
        v.x = (v.x-mean)*rstd; v.y = (v.y-mean)*rstd;
        v.z = (v.z-mean)*rstd; v.w = (v.w-mean)*rstd;
        *reinterpret_cast<float4*>(&Xs[r*132 + cq*4]) = v;
    }
    #pragma unroll
    for (int i = 0; i < 16; i++) {                // U [128][32] -> Ust[k][c]
        int f = t + i*TPB;
        int c = f >> 5, k = f & 31;
        Ust[k*134 + c] = U[f];
    }
    for (int i = t; i < JD*KD; i += TPB) Yps[i] = g_yp[b*JD*KD + i];
    __syncthreads();

    const int rg = t >> 4, cg = t & 15;
    { // phase 1: Xp = relu(X@U), thread = 4 rows x 2 cols, k-packed over c
        u64 acc[4][2] = {};
        #pragma unroll 8
        for (int c2 = 0; c2 < 64; c2++) {
            u64 a2[4], b2[2];
            #pragma unroll
            for (int m = 0; m < 4; m++)
                a2[m] = *reinterpret_cast<const u64*>(&Xs[(rg*4+m)*132 + 2*c2]);
            #pragma unroll
            for (int d = 0; d < 2; d++)
                b2[d] = *reinterpret_cast<const u64*>(&Ust[(cg*2+d)*134 + 2*c2]);
            #pragma unroll
            for (int m = 0; m < 4; m++) {
                FMA2(acc[m][0], a2[m], b2[0]);
                FMA2(acc[m][1], a2[m], b2[1]);
            }
        }
        #pragma unroll
        for (int m = 0; m < 4; m++) {
            float2 p0 = UPK(acc[m][0]), p1 = UPK(acc[m][1]);
            float v0 = fmaxf(p0.x + p0.y, 0.f);
            float v1 = fmaxf(p1.x + p1.y, 0.f);
            *reinterpret_cast<u64*>(&Xps[(rg*4+m)*34 + cg*2]) = PK2(v0, v1);
        }
    }
    __syncthreads();

    { // phase 2: I rows; thread = (node r, 10 j's), pair-packed dot
        const int r = t & 63, js = t >> 6;
        u64 xp2[16];
        #pragma unroll
        for (int p = 0; p < 16; p++)
            xp2[p] = *reinterpret_cast<const u64*>(&Xps[r*34 + 2*p]);
        #pragma unroll
        for (int jj = 0; jj < 10; jj++) {
            int j = js*10 + jj;
            u64 a = 0;
            #pragma unroll
            for (int p = 0; p < 16; p++)
                FMA2(a, xp2[p], *reinterpret_cast<const u64*>(&Yps[j*32 + 2*p]));
            float2 pr = UPK(a);
            Is[r*41 + j] = pr.x + pr.y;
        }
    }
    __syncthreads();

    float* gP = g_P + (long)base * JD;
    for (int o = t; o < 64*JD; o += TPB) gP[o] = Is[(o/JD)*41 + (o%JD)];
    if (t < JD) {
        float m = 0.f;
        for (int r = 0; r < 64; r++) m = fmaxf(m, Is[r*41 + t]);
        atomicMax((int*)(g_M + layer*NB*JD + b*JD + t), __float_as_int(m));
    }
}

// accumulate column sum of exp(I-M); read-only on g_P
__global__ void k_sumexp(int layer)
{
    __shared__ float Ms[JD], sj[JD];
    const int t = threadIdx.x;
    const int b = blockIdx.x >> 5, chunk = blockIdx.x & 31;    // 128 nodes/block
    const long base = ((long)b*NPG + chunk*128) * JD;
    if (t < JD) { Ms[t] = g_M[layer*NB*JD + b*JD + t]; sj[t] = 0.f; }
    __syncthreads();
    float loc[5] = {0,0,0,0,0};
    #pragma unroll
    for (int i = 0; i < 20; i++) {                // 128*40 / 256
        int o = t + i*TPB;
        int j = o % JD;
        loc[j >> 3] += __expf(g_P[base + o] - Ms[j]);
    }
    const int jc = t & 7;
    #pragma unroll
    for (int i = 0; i < 5; i++) atomicAdd(&sj[i*8 + jc], loc[i]);
    __syncthreads();
    if (t < JD) atomicAdd(&g_S[layer*NB*JD + b*JD + t], sj[t]);
}

// E = exp(I-M); H = relu(E @ (y_p/S)); hC = H@V^T; gate; x = (1-z)x + z*hC
__global__ void k_h_gate(const float* __restrict__ V, const float* __restrict__ gW,
                         const float* __restrict__ gb, int layer)
{
    extern __shared__ float sm[];
    float* Es   = sm;                 // [64][41]  exp(I-M)
    float* Yps2 = Es + 64*41;         // [40][32]  y_p/S
    float* Hs   = Yps2 + JD*KD;       // [64][34]
    float* Vst  = Hs + 64*34;         // [32][132] (k-major V^T)
    float* invS = Vst + KD*132;       // [40]
    float* Ms   = invS + JD;          // [40]
    float* gws  = Ms + JD;            // [256]
    const int t = threadIdx.x;
    const int b = blockIdx.x >> 6, tile = blockIdx.x & 63;
    const int base = b*NPG + tile*64;
    float mean = 0.f, rstd = 1.f;
    if (layer == 0) node_ln(mean, rstd);
    const float gb0 = gb[0];

    if (t < JD) {
        invS[t] = 1.f / g_S[layer*NB*JD + b*JD + t];
        Ms[t]   = g_M[layer*NB*JD + b*JD + t];
    }
    gws[t] = gW[t];
    __syncthreads();
    for (int i = t; i < JD*KD; i += TPB) Yps2[i] = g_yp[b*JD*KD + i] * invS[i >> 5];
    #pragma unroll
    for (int i = 0; i < 4; i++) {                  // V [128][32] -> Vst[k][c]
        int f = t + i*TPB;
        int c = f >> 3, kq = f & 7;
        float4 v = reinterpret_cast<const float4*>(V)[c*(KD/4) + kq];
        Vst[(kq*4+0)*132 + c] = v.x;
        Vst[(kq*4+1)*132 + c] = v.y;
        Vst[(kq*4+2)*132 + c] = v.z;
        Vst[(kq*4+3)*132 + c] = v.w;
    }
    for (int o = t; o < 64*JD; o += TPB) {
        int r = o / JD, j = o - r*JD;
        Es[r*41 + j] = __expf(g_P[(long)base*JD + o] - Ms[j]);
    }
    __syncthreads();

    const int rg = t >> 4, cg = t & 15;
    { // phase 1: H[64][32] = relu(E @ Yps2), col-pair f32x2
        u64 acc[4] = {};
        #pragma unroll 8
        for (int j = 0; j < JD; j++) {
            u64 b2 = *reinterpret_cast<const u64*>(&Yps2[j*32 + cg*2]);
            #pragma unroll
            for (int m = 0; m < 4; m++)
                FMA2(acc[m], SPLAT(Es[(rg*4+m)*41 + j]), b2);
        }
        #pragma unroll
        for (int m = 0; m < 4; m++) {
            float2 p = UPK(acc[m]);
            *reinterpret_cast<u64*>(&Hs[(rg*4+m)*34 + cg*2]) =
                PK2(fmaxf(p.x, 0.f), fmaxf(p.y, 0.f));
        }
    }
    __syncthreads();

    // phase 2: hC[64][128], strided col pairs (2cg+32u); then gate + update
    u64 hcp[4][4] = {};
    #pragma unroll 4
    for (int k = 0; k < KD; k++) {
        u64 av[4], bv[4];
        #pragma unroll
        for (int m = 0; m < 4; m++) av[m] = SPLAT(Hs[(rg*4+m)*34 + k]);
        #pragma unroll
        for (int u = 0; u < 4; u++)
            bv[u] = *reinterpret_cast<const u64*>(&Vst[k*132 + cg*2 + 32*u]);
        #pragma unroll
        for (int m = 0; m < 4; m++)
            #pragma unroll
            for (int u = 0; u < 4; u++) FMA2(hcp[m][u], av[m], bv[u]);
    }

    float gp[4], xvf[4][8], hcf[4][8];
    #pragma unroll
    for (int m = 0; m < 4; m++) {
        int row = base + rg*4 + m;
        float p = 0.f;
        #pragma unroll
        for (int u = 0; u < 4; u++) {
            float2 hv = UPK(hcp[m][u]);
            float2 xr = *reinterpret_cast<const float2*>(&g_t[row*CD + cg*2 + 32*u]);
            float x0 = (xr.x - mean) * rstd, x1 = (xr.y - mean) * rstd;
            hcf[m][2*u] = hv.x; hcf[m][2*u+1] = hv.y;
            xvf[m][2*u] = x0;   xvf[m][2*u+1] = x1;
            p = fmaf(x0, gws[cg*2 + 32*u],      p);
            p = fmaf(x1, gws[cg*2 + 32*u + 1],  p);
            p = fmaf(hv.x, gws[CD + cg*2 + 32*u],     p);
            p = fmaf(hv.y, gws[CD + cg*2 + 32*u + 1], p);
        }
        gp[m] = p;
    }
    #pragma unroll
    for (int off = 8; off; off >>= 1)
        #pragma unroll
        for (int m = 0; m < 4; m++)
            gp[m] += __shfl_xor_sync(0xffffffffu, gp[m], off);
    #pragma unroll
    for (int m = 0; m < 4; m++) {
        float z = 1.f / (1.f + __expf(-(gp[m] + gb0)));
        int row = base + rg*4 + m;
        #pragma unroll
        for (int u = 0; u < 4; u++) {
            float o0 = fmaf(z, hcf[m][2*u]   - xvf[m][2*u],   xvf[m][2*u]);
            float o1 = fmaf(z, hcf[m][2*u+1] - xvf[m][2*u+1], xvf[m][2*u+1]);
            *reinterpret_cast<float2*>(&g_t[row*CD + cg*2 + 32*u]) = make_float2(o0, o1);
        }
    }
}

// x_p = relu(x@U); out = sigmoid(x_p . (x_p @ G))
__global__ void k_final(const float* __restrict__ U, float* __restrict__ out)
{
    extern __shared__ float sm[];
    float* Xs  = sm;               // [64][132]
    float* Ust = Xs + 64*132;      // [32][134]
    float* Xps = Ust + 32*134;     // [64][34]
    float* Gs  = Xps + 64*34;      // [32][32]
    const int t = threadIdx.x;
    const int b = blockIdx.x >> 6, tile = blockIdx.x & 63;
    const int base = b*NPG + tile*64;

    #pragma unroll
    for (int i = 0; i < 8; i++) {
        int f = t + i*TPB;
        int r = f >> 5, cq = f & 31;
        float4 v = reinterpret_cast<const float4*>(g_t)[(base + r)*(CD/4) + cq];
        *reinterpret_cast<float4*>(&Xs[r*132 + cq*4]) = v;
    }
    #pragma unroll
    for (int i = 0; i < 16; i++) {
        int f = t + i*TPB;
        int c = f >> 5, k = f & 31;
        Ust[k*134 + c] = U[f];
    }
    for (int i = t; i < KD*KD; i += TPB) Gs[i] = g_G[b*KD*KD + i];
    __syncthreads();

    const int rg = t >> 4, cg = t & 15;
    { // Xp = relu(X@U), k-packed over c
        u64 acc[4][2] = {};
        #pragma unroll 8
        for (int c2 = 0; c2 < 64; c2++) {
            u64 a2[4], b2[2];
            #pragma unroll
            for (int m = 0; m < 4; m++)
                a2[m] = *reinterpret_cast<const u64*>(&Xs[(rg*4+m)*132 + 2*c2]);
            #pragma unroll
            for (int d = 0; d < 2; d++)
                b2[d] = *reinterpret_cast<const u64*>(&Ust[(cg*2+d)*134 + 2*c2]);
            #pragma unroll
            for (int m = 0; m < 4; m++) {
                FMA2(acc[m][0], a2[m], b2[0]);
                FMA2(acc[m][1], a2[m], b2[1]);
            }
        }
        #pragma unroll
        for (int m = 0; m < 4; m++) {
            float2 p0 = UPK(acc[m][0]), p1 = UPK(acc[m][1]);
            float v0 = fmaxf(p0.x + p0.y, 0.f);
            float v1 = fmaxf(p1.x + p1.y, 0.f);
            *reinterpret_cast<u64*>(&Xps[(rg*4+m)*34 + cg*2]) = PK2(v0, v1);
        }
    }
    __syncthreads();
    { // tvec = Xp@G (col pairs), dot with Xp, reduce over 16 lanes
        u64 acc[4] = {};
        #pragma unroll
        for (int k = 0; k < KD; k++) {
            u64 b2 = *reinterpret_cast<const u64*>(&Gs[k*32 + cg*2]);
            #pragma unroll
            for (int m = 0; m < 4; m++)
                FMA2(acc[m], SPLAT(Xps[(rg*4+m)*34 + k]), b2);
        }
        float part[4];
        #pragma unroll
        for (int m = 0; m < 4; m++) {
            float2 p = UPK(acc[m]);
            part[m] = p.x * Xps[(rg*4+m)*34 + cg*2]
                    + p.y * Xps[(rg*4+m)*34 + cg*2 + 1];
        }
        #pragma unroll
        for (int off = 8; off; off >>= 1)
            #pragma unroll
            for (int m = 0; m < 4; m++)
                part[m] += __shfl_xor_sync(0xffffffffu, part[m], off);
        if (cg == 0) {
            #pragma unroll
            for (int m = 0; m < 4; m++)
                out[base + rg*4 + m] = 1.f / (1.f + __expf(-part[m]));
        }
    }
}

// ---------------------------------------------------------------------------
extern "C" void kernel_launch(void* const* d_in, const int* in_sizes, int n_in,
                              void* d_out, int out_size)
{
    (void)in_sizes; (void)n_in; (void)out_size;
    const float* nf   = (const float*)d_in[0];
    const float* frag = (const float*)d_in[1];
    const float* Wi   = (const float*)d_in[2];
    const float* bi   = (const float*)d_in[3];
    const float* U    = (const float*)d_in[4];
    const float* V    = (const float*)d_in[5];
    const float* q    = (const float*)d_in[6];
    const float* gW   = (const float*)d_in[7];
    const float* gb   = (const float*)d_in[8];
    float* out = (float*)d_out;

    const int SM_GEMM = (64*68 + 64*132 + 128 + 16) * 4;                  // 51776
    const int SM_XPI  = (64*132 + 32*134 + 64*34 + JD*KD) * 4 + 64*41*4;  // ~75264
    const int SM_HG   = (64*41 + JD*KD + 64*34 + KD*132 + JD + JD + 256)*4; // 42560
    const int SM_FIN  = (64*132 + 32*134 + 64*34 + KD*KD) * 4;            // 63744

    cudaFuncSetAttribute((const void*)k_in_gemm, cudaFuncAttributeMaxDynamicSharedMemorySize, SM_GEMM);
    cudaFuncSetAttribute((const void*)k_xp_I,    cudaFuncAttributeMaxDynamicSharedMemorySize, SM_XPI);
    cudaFuncSetAttribute((const void*)k_h_gate,  cudaFuncAttributeMaxDynamicSharedMemorySize, SM_HG);
    cudaFuncSetAttribute((const void*)k_final,   cudaFuncAttributeMaxDynamicSharedMemorySize, SM_FIN);

    k_zero<<<10, TPB>>>();
    k_in_gemm<<<NTOT/64, TPB, SM_GEMM>>>(nf, Wi, bi, 0);
    k_in_gemm<<<NB*JD/64, TPB, SM_GEMM>>>(frag, Wi, bi, 1);
    k_yp<<<NB*5, TPB>>>(V, q);
    k_G<<<NB, TPB>>>();

    for (int l = 0; l < 2; l++) {
        k_xp_I  <<<NTOT/64,  TPB, SM_XPI>>>(U, l);
        k_sumexp<<<NTOT/128, TPB>>>(l);
        k_h_gate<<<NTOT/64,  TPB, SM_HG>>>(V, gW, gb, l);
    }
    k_final<<<NTOT/64, TPB, SM_FIN>>>(U, out);
}

// round 13
// speedup vs baseline: 1.8940x; 1.6414x over previous
#include <cuda_runtime.h>
#include <math.h>

#define NB    32
#define NPG   4096
#define NTOT  (NB*NPG)      // 131072 nodes
#define FIN   64
#define CD    128
#define KD    32
#define JD    40
#define EPSV  1e-5f
#define TPB   256

typedef unsigned long long u64;

__device__ __forceinline__ u64 PK2(float lo, float hi) {
    u64 r; asm("mov.b64 %0, {%1,%2};" : "=l"(r) : "f"(lo), "f"(hi)); return r;
}
__device__ __forceinline__ u64 SPLAT(float v) {
    u64 r; asm("mov.b64 %0, {%1,%1};" : "=l"(r) : "f"(v)); return r;
}
__device__ __forceinline__ void FMA2(u64& d, u64 a, u64 b) {
    asm("fma.rn.f32x2 %0, %1, %2, %0;" : "+l"(d) : "l"(a), "l"(b));
}
__device__ __forceinline__ float2 UPK(u64 v) {
    float lo, hi; asm("mov.b64 {%0,%1}, %2;" : "=f"(lo), "=f"(hi) : "l"(v));
    return make_float2(lo, hi);
}

// ---------------- scratch (device globals: no allocs allowed) ----------------
__device__ float  g_t [NTOT*CD];     // t = nf@W^T+b, later in-place gated x
__device__ float  g_P [NTOT*JD];     // raw I per layer
__device__ float  g_ty[NB*JD*CD];    // frag pre-LN
__device__ float  g_yp[NB*JD*KD];    // y_p (raw)
__device__ float  g_G [NB*KD*KD];    // y_p^T y_p per graph
__device__ double g_red[4];          // node sum/sumsq, frag sum/sumsq
__device__ float  g_ln[4];           // node mean,rstd ; frag mean,rstd
__device__ float  g_M[2*NB*JD];      // per-layer column max (I>=0 so init 0 ok)
__device__ float  g_S[2*NB*JD];      // per-layer column sum-exp

// ---------------------------------------------------------------------------
__global__ void k_zero() {
    int t = blockIdx.x*blockDim.x + threadIdx.x;
    if (t < 4) g_red[t] = 0.0;
    if (t < 2*NB*JD) { g_M[t] = 0.f; g_S[t] = 0.f; }
}

// out[row][c] = sum_d in[row][d]*W[c][d] + b[c]; 64 rows x 128 cols per block.
// f32x2: strided column pairs (2cg + 32u) -> conflict-free LDS64 on Ws.
__global__ void k_in_gemm(const float* __restrict__ in, const float* __restrict__ W,
                          const float* __restrict__ bias, int which)
{
    extern __shared__ float sm[];
    float* As = sm;              // [64][68]  input tile
    float* Ws = As + 64*68;      // [64][132] W^T, k-major
    float* bs = Ws + 64*132;     // [128]
    float* r1 = bs + 128;        // [8]
    float* r2 = r1 + 8;          // [8]
    float* outg = which ? g_ty : g_t;
    const int slot = which * 2;
    const int t = threadIdx.x;
    const int base = blockIdx.x * 64;

    #pragma unroll
    for (int i = 0; i < 4; i++) {                 // A tile: 64x64 floats
        int f = t + i*TPB;
        int r = f >> 4, cq = f & 15;
        float4 v = reinterpret_cast<const float4*>(in)[(base + r)*(FIN/4) + cq];
        *reinterpret_cast<float4*>(&As[r*68 + cq*4]) = v;
    }
    #pragma unroll
    for (int i = 0; i < 8; i++) {                 // W [128][64] -> Ws[k][c]
        int f = t + i*TPB;
        int c = f >> 4, kq = f & 15;
        float4 v = reinterpret_cast<const float4*>(W)[c*(FIN/4) + kq];
        Ws[(kq*4+0)*132 + c] = v.x;
        Ws[(kq*4+1)*132 + c] = v.y;
        Ws[(kq*4+2)*132 + c] = v.z;
        Ws[(kq*4+3)*132 + c] = v.w;
    }
    if (t < CD) bs[t] = bias[t];
    __syncthreads();

    const int rg = t >> 4, cg = t & 15;           // 4 rows x 4 strided pairs
    u64 acc[4][4] = {};

    #pragma unroll 4
    for (int k = 0; k < 64; k++) {
        u64 av[4], bv[4];
        #pragma unroll
        for (int m = 0; m < 4; m++) av[m] = SPLAT(As[(rg*4+m)*68 + k]);
        #pragma unroll
        for (int u = 0; u < 4; u++)
            bv[u] = *reinterpret_cast<const u64*>(&Ws[k*132 + cg*2 + 32*u]);
        #pragma unroll
        for (int m = 0; m < 4; m++)
            #pragma unroll
            for (int u = 0; u < 4; u++) FMA2(acc[m][u], av[m], bv[u]);
    }

    float s1 = 0.f, s2 = 0.f;
    #pragma unroll
    for (int m = 0; m < 4; m++) {
        int row = base + rg*4 + m;
        #pragma unroll
        for (int u = 0; u < 4; u++) {
            float2 p = UPK(acc[m][u]);
            float o0 = p.x + bs[cg*2 + 32*u];
            float o1 = p.y + bs[cg*2 + 32*u + 1];
            s1 += o0 + o1;
            s2 = fmaf(o0, o0, fmaf(o1, o1, s2));
            *reinterpret_cast<float2*>(&outg[row*CD + cg*2 + 32*u]) = make_float2(o0, o1);
        }
    }
    #pragma unroll
    for (int off = 16; off; off >>= 1) {
        s1 += __shfl_xor_sync(0xffffffffu, s1, off);
        s2 += __shfl_xor_sync(0xffffffffu, s2, off);
    }
    if ((t & 31) == 0) { r1[t>>5] = s1; r2[t>>5] = s2; }
    __syncthreads();
    if (t == 0) {
        float a = 0.f, b = 0.f;
        #pragma unroll
        for (int w = 0; w < 8; w++) { a += r1[w]; b += r2[w]; }
        atomicAdd(&g_red[slot],   (double)a);
        atomicAdd(&g_red[slot+1], (double)b);
    }
}

// One thread: fold double sums into float mean/rstd (FP64 confined here).
__global__ void k_finalize() {
    if (threadIdx.x == 0) {
        double ne = (double)NTOT * CD;
        double m  = g_red[0] / ne;
        double v  = g_red[1] / ne - m*m;
        g_ln[0] = (float)m;
        g_ln[1] = (float)(1.0 / sqrt(v + (double)EPSV));
        double nf = (double)NB * JD * CD;
        double mf = g_red[2] / nf;
        double vf = g_red[3] / nf - mf*mf;
        g_ln[2] = (float)mf;
        g_ln[3] = (float)(1.0 / sqrt(vf + (double)EPSV));
    }
}

// y_p = relu(q * relu(LN(ty) @ V)); grid NB*5, each block = 8 j rows of one graph.
__global__ void k_yp(const float* __restrict__ V, const float* __restrict__ q)
{
    __shared__ float ysn[8*132];
    __shared__ float Vs[CD*KD];
    __shared__ float qs[KD];
    const int t = threadIdx.x;
    const int b = blockIdx.x / 5, jg = blockIdx.x % 5;
    const float mf = g_ln[2], rf = g_ln[3];

    #pragma unroll
    for (int i = 0; i < 4; i++) {                  // 8 rows x 128 = 1024 floats
        int f = t + i*TPB;
        int r = f >> 7, c = f & 127;
        ysn[r*132 + c] = (g_ty[(b*JD + jg*8 + r)*CD + c] - mf) * rf;
    }
    #pragma unroll
    for (int i = 0; i < 16; i++) Vs[t + i*TPB] = V[t + i*TPB];
    if (t < KD) qs[t] = q[t];
    __syncthreads();

    const int j = t >> 5, k = t & 31;              // one output per thread
    float a0 = 0.f, a1 = 0.f, a2 = 0.f, a3 = 0.f;
    #pragma unroll
    for (int d = 0; d < CD; d += 4) {
        a0 = fmaf(ysn[j*132 + d    ], Vs[(d    )*KD + k], a0);
        a1 = fmaf(ysn[j*132 + d + 1], Vs[(d + 1)*KD + k], a1);
        a2 = fmaf(ysn[j*132 + d + 2], Vs[(d + 2)*KD + k], a2);
        a3 = fmaf(ysn[j*132 + d + 3], Vs[(d + 3)*KD + k], a3);
    }
    float acc = (a0 + a1) + (a2 + a3);
    g_yp[b*JD*KD + (jg*8 + j)*KD + k] = fmaxf(qs[k] * fmaxf(acc, 0.f), 0.f);
}

// G = y_p^T y_p per graph; grid NB
__global__ void k_G()
{
    __shared__ float yps[JD*KD];
    const int t = threadIdx.x, b = blockIdx.x;
    for (int i = t; i < JD*KD; i += TPB) yps[i] = g_yp[b*JD*KD + i];
    __syncthreads();
    #pragma unroll
    for (int i = 0; i < 4; i++) {
        int o = t + i*TPB;
        int k1 = o >> 5, k2 = o & 31;
        float acc = 0.f;
        #pragma unroll
        for (int j = 0; j < JD; j++) acc = fmaf(yps[j*KD+k1], yps[j*KD+k2], acc);
        g_G[b*KD*KD + o] = acc;
    }
}

// 64 nodes/block: x_p = relu(x@U); I = x_p @ y_p^T; write I; atomicMax column max
__global__ void k_xp_I(const float* __restrict__ U, int layer)
{
    extern __shared__ float sm[];
    float* Xs  = sm;               // [64][132]
    float* Ust = Xs + 64*132;      // [32][134]  U transposed, k-major over c
    float* Xps = Ust + 32*134;     // [64][34]
    float* Yps = Xps + 64*34;      // [40][32]
    float* Is  = Yps + JD*KD;      // [64][41]
    const int t = threadIdx.x;
    const int b = blockIdx.x >> 6, tile = blockIdx.x & 63;
    const int base = b*NPG + tile*64;
    const float mean = layer == 0 ? g_ln[0] : 0.f;
    const float rstd = layer == 0 ? g_ln[1] : 1.f;

    #pragma unroll
    for (int i = 0; i < 8; i++) {
        int f = t + i*TPB;
        int r = f >> 5, cq = f & 31;
        float4 v = reinterpret_cast<const float4*>(g_t)[(base + r)*(CD/4) + cq];
        v.x = (v.x-mean)*rstd; v.y = (v.y-mean)*rstd;
        v.z = (v.z-mean)*rstd; v.w = (v.w-mean)*rstd;
        *reinterpret_cast<float4*>(&Xs[r*132 + cq*4]) = v;
    }
    #pragma unroll
    for (int i = 0; i < 16; i++) {                // U [128][32] -> Ust[k][c]
        int f = t + i*TPB;
        int c = f >> 5, k = f & 31;
        Ust[k*134 + c] = U[f];
    }
    for (int i = t; i < JD*KD; i += TPB) Yps[i] = g_yp[b*JD*KD + i];
    __syncthreads();

    const int rg = t >> 4, cg = t & 15;
    { // phase 1: Xp = relu(X@U), thread = 4 rows x 2 cols, k-packed over c
        u64 acc[4][2] = {};
        #pragma unroll 8
        for (int c2 = 0; c2 < 64; c2++) {
            u64 a2[4], b2[2];
            #pragma unroll
            for (int m = 0; m < 4; m++)
                a2[m] = *reinterpret_cast<const u64*>(&Xs[(rg*4+m)*132 + 2*c2]);
            #pragma unroll
            for (int d = 0; d < 2; d++)
                b2[d] = *reinterpret_cast<const u64*>(&Ust[(cg*2+d)*134 + 2*c2]);
            #pragma unroll
            for (int m = 0; m < 4; m++) {
                FMA2(acc[m][0], a2[m], b2[0]);
                FMA2(acc[m][1], a2[m], b2[1]);
            }
        }
        #pragma unroll
        for (int m = 0; m < 4; m++) {
            float2 p0 = UPK(acc[m][0]), p1 = UPK(acc[m][1]);
            float v0 = fmaxf(p0.x + p0.y, 0.f);
            float v1 = fmaxf(p1.x + p1.y, 0.f);
            *reinterpret_cast<u64*>(&Xps[(rg*4+m)*34 + cg*2]) = PK2(v0, v1);
        }
    }
    __syncthreads();

    { // phase 2: I rows; thread = (node r, 10 j's), pair-packed dot
        const int r = t & 63, js = t >> 6;
        u64 xp2[16];
        #pragma unroll
        for (int p = 0; p < 16; p++)
            xp2[p] = *reinterpret_cast<const u64*>(&Xps[r*34 + 2*p]);
        #pragma unroll
        for (int jj = 0; jj < 10; jj++) {
            int j = js*10 + jj;
            u64 a = 0;
            #pragma unroll
            for (int p = 0; p < 16; p++)
                FMA2(a, xp2[p], *reinterpret_cast<const u64*>(&Yps[j*32 + 2*p]));
            float2 pr = UPK(a);
            Is[r*41 + j] = pr.x + pr.y;
        }
    }
    __syncthreads();

    float* gP = g_P + (long)base * JD;
    for (int o = t; o < 64*JD; o += TPB) gP[o] = Is[(o/JD)*41 + (o%JD)];
    if (t < JD) {
        float m = 0.f;
        for (int r = 0; r < 64; r++) m = fmaxf(m, Is[r*41 + t]);
        atomicMax((int*)(g_M + layer*NB*JD + b*JD + t), __float_as_int(m));
    }
}

// accumulate column sum of exp(I-M); read-only on g_P
__global__ void k_sumexp(int layer)
{
    __shared__ float Ms[JD], sj[JD];
    const int t = threadIdx.x;
    const int b = blockIdx.x >> 5, chunk = blockIdx.x & 31;    // 128 nodes/block
    const long base = ((long)b*NPG + chunk*128) * JD;
    if (t < JD) { Ms[t] = g_M[layer*NB*JD + b*JD + t]; sj[t] = 0.f; }
    __syncthreads();
    float loc[5] = {0,0,0,0,0};
    #pragma unroll
    for (int i = 0; i < 20; i++) {                // 128*40 / 256
        int o = t + i*TPB;
        int j = o % JD;
        loc[j >> 3] += __expf(g_P[base + o] - Ms[j]);
    }
    const int jc = t & 7;
    #pragma unroll
    for (int i = 0; i < 5; i++) atomicAdd(&sj[i*8 + jc], loc[i]);
    __syncthreads();
    if (t < JD) atomicAdd(&g_S[layer*NB*JD + b*JD + t], sj[t]);
}

// E = exp(I-M); H = relu(E @ (y_p/S)); hC = H@V^T; gate; x = (1-z)x + z*hC
__global__ void k_h_gate(const float* __restrict__ V, const float* __restrict__ gW,
                         const float* __restrict__ gb, int layer)
{
    extern __shared__ float sm[];
    float* Es   = sm;                 // [64][41]  exp(I-M)
    float* Yps2 = Es + 64*41;         // [40][32]  y_p/S
    float* Hs   = Yps2 + JD*KD;       // [64][34]
    float* Vst  = Hs + 64*34;         // [32][132] (k-major V^T)
    float* invS = Vst + KD*132;       // [40]
    float* Ms   = invS + JD;          // [40]
    float* gws  = Ms + JD;            // [256]
    const int t = threadIdx.x;
    const int b = blockIdx.x >> 6, tile = blockIdx.x & 63;
    const int base = b*NPG + tile*64;
    const float mean = layer == 0 ? g_ln[0] : 0.f;
    const float rstd = layer == 0 ? g_ln[1] : 1.f;
    const float gb0 = gb[0];

    if (t < JD) {
        invS[t] = 1.f / g_S[layer*NB*JD + b*JD + t];
        Ms[t]   = g_M[layer*NB*JD + b*JD + t];
    }
    gws[t] = gW[t];
    __syncthreads();
    for (int i = t; i < JD*KD; i += TPB) Yps2[i] = g_yp[b*JD*KD + i] * invS[i >> 5];
    #pragma unroll
    for (int i = 0; i < 4; i++) {                  // V [128][32] -> Vst[k][c]
        int f = t + i*TPB;
        int c = f >> 3, kq = f & 7;
        float4 v = reinterpret_cast<const float4*>(V)[c*(KD/4) + kq];
        Vst[(kq*4+0)*132 + c] = v.x;
        Vst[(kq*4+1)*132 + c] = v.y;
        Vst[(kq*4+2)*132 + c] = v.z;
        Vst[(kq*4+3)*132 + c] = v.w;
    }
    for (int o = t; o < 64*JD; o += TPB) {
        int r = o / JD, j = o - r*JD;
        Es[r*41 + j] = __expf(g_P[(long)base*JD + o] - Ms[j]);
    }
    __syncthreads();

    const int rg = t >> 4, cg = t & 15;
    { // phase 1: H[64][32] = relu(E @ Yps2), col-pair f32x2
        u64 acc[4] = {};
        #pragma unroll 8
        for (int j = 0; j < JD; j++) {
            u64 b2 = *reinterpret_cast<const u64*>(&Yps2[j*32 + cg*2]);
            #pragma unroll
            for (int m = 0; m < 4; m++)
                FMA2(acc[m], SPLAT(Es[(rg*4+m)*41 + j]), b2);
        }
        #pragma unroll
        for (int m = 0; m < 4; m++) {
            float2 p = UPK(acc[m]);
            *reinterpret_cast<u64*>(&Hs[(rg*4+m)*34 + cg*2]) =
                PK2(fmaxf(p.x, 0.f), fmaxf(p.y, 0.f));
        }
    }
    __syncthreads();

    // phase 2: hC[64][128], strided col pairs (2cg+32u); then gate + update
    u64 hcp[4][4] = {};
    #pragma unroll 4
    for (int k = 0; k < KD; k++) {
        u64 av[4], bv[4];
        #pragma unroll
        for (int m = 0; m < 4; m++) av[m] = SPLAT(Hs[(rg*4+m)*34 + k]);
        #pragma unroll
        for (int u = 0; u < 4; u++)
            bv[u] = *reinterpret_cast<const u64*>(&Vst[k*132 + cg*2 + 32*u]);
        #pragma unroll
        for (int m = 0; m < 4; m++)
            #pragma unroll
            for (int u = 0; u < 4; u++) FMA2(hcp[m][u], av[m], bv[u]);
    }

    float gp[4], xvf[4][8], hcf[4][8];
    #pragma unroll
    for (int m = 0; m < 4; m++) {
        int row = base + rg*4 + m;
        float p = 0.f;
        #pragma unroll
        for (int u = 0; u < 4; u++) {
            float2 hv = UPK(hcp[m][u]);
            float2 xr = *reinterpret_cast<const float2*>(&g_t[row*CD + cg*2 + 32*u]);
            float x0 = (xr.x - mean) * rstd, x1 = (xr.y - mean) * rstd;
            hcf[m][2*u] = hv.x; hcf[m][2*u+1] = hv.y;
            xvf[m][2*u] = x0;   xvf[m][2*u+1] = x1;
            p = fmaf(x0, gws[cg*2 + 32*u],      p);
            p = fmaf(x1, gws[cg*2 + 32*u + 1],  p);
            p = fmaf(hv.x, gws[CD + cg*2 + 32*u],     p);
            p = fmaf(hv.y, gws[CD + cg*2 + 32*u + 1], p);
        }
        gp[m] = p;
    }
    #pragma unroll
    for (int off = 8; off; off >>= 1)
        #pragma unroll
        for (int m = 0; m < 4; m++)
            gp[m] += __shfl_xor_sync(0xffffffffu, gp[m], off);
    #pragma unroll
    for (int m = 0; m < 4; m++) {
        float z = 1.f / (1.f + __expf(-(gp[m] + gb0)));
        int row = base + rg*4 + m;
        #pragma unroll
        for (int u = 0; u < 4; u++) {
            float o0 = fmaf(z, hcf[m][2*u]   - xvf[m][2*u],   xvf[m][2*u]);
            float o1 = fmaf(z, hcf[m][2*u+1] - xvf[m][2*u+1], xvf[m][2*u+1]);
            *reinterpret_cast<float2*>(&g_t[row*CD + cg*2 + 32*u]) = make_float2(o0, o1);
        }
    }
}

// x_p = relu(x@U); out = sigmoid(x_p . (x_p @ G))
__global__ void k_final(const float* __restrict__ U, float* __restrict__ out)
{
    extern __shared__ float sm[];
    float* Xs  = sm;               // [64][132]
    float* Ust = Xs + 64*132;      // [32][134]
    float* Xps = Ust + 32*134;     // [64][34]
    float* Gs  = Xps + 64*34;      // [32][32]
    const int t = threadIdx.x;
    const int b = blockIdx.x >> 6, tile = blockIdx.x & 63;
    const int base = b*NPG + tile*64;

    #pragma unroll
    for (int i = 0; i < 8; i++) {
        int f = t + i*TPB;
        int r = f >> 5, cq = f & 31;
        float4 v = reinterpret_cast<const float4*>(g_t)[(base + r)*(CD/4) + cq];
        *reinterpret_cast<float4*>(&Xs[r*132 + cq*4]) = v;
    }
    #pragma unroll
    for (int i = 0; i < 16; i++) {
        int f = t + i*TPB;
        int c = f >> 5, k = f & 31;
        Ust[k*134 + c] = U[f];
    }
    for (int i = t; i < KD*KD; i += TPB) Gs[i] = g_G[b*KD*KD + i];
    __syncthreads();

    const int rg = t >> 4, cg = t & 15;
    { // Xp = relu(X@U), k-packed over c
        u64 acc[4][2] = {};
        #pragma unroll 8
        for (int c2 = 0; c2 < 64; c2++) {
            u64 a2[4], b2[2];
            #pragma unroll
            for (int m = 0; m < 4; m++)
                a2[m] = *reinterpret_cast<const u64*>(&Xs[(rg*4+m)*132 + 2*c2]);
            #pragma unroll
            for (int d = 0; d < 2; d++)
                b2[d] = *reinterpret_cast<const u64*>(&Ust[(cg*2+d)*134 + 2*c2]);
            #pragma unroll
            for (int m = 0; m < 4; m++) {
                FMA2(acc[m][0], a2[m], b2[0]);
                FMA2(acc[m][1], a2[m], b2[1]);
            }
        }
        #pragma unroll
        for (int m = 0; m < 4; m++) {
            float2 p0 = UPK(acc[m][0]), p1 = UPK(acc[m][1]);
            float v0 = fmaxf(p0.x + p0.y, 0.f);
            float v1 = fmaxf(p1.x + p1.y, 0.f);
            *reinterpret_cast<u64*>(&Xps[(rg*4+m)*34 + cg*2]) = PK2(v0, v1);
        }
    }
    __syncthreads();
    { // tvec = Xp@G (col pairs), dot with Xp, reduce over 16 lanes
        u64 acc[4] = {};
        #pragma unroll
        for (int k = 0; k < KD; k++) {
            u64 b2 = *reinterpret_cast<const u64*>(&Gs[k*32 + cg*2]);
            #pragma unroll
            for (int m = 0; m < 4; m++)
                FMA2(acc[m], SPLAT(Xps[(rg*4+m)*34 + k]), b2);
        }
        float part[4];
        #pragma unroll
        for (int m = 0; m < 4; m++) {
            float2 p = UPK(acc[m]);
            part[m] = p.x * Xps[(rg*4+m)*34 + cg*2]
                    + p.y * Xps[(rg*4+m)*34 + cg*2 + 1];
        }
        #pragma unroll
        for (int off = 8; off; off >>= 1)
            #pragma unroll
            for (int m = 0; m < 4; m++)
                part[m] += __shfl_xor_sync(0xffffffffu, part[m], off);
        if (cg == 0) {
            #pragma unroll
            for (int m = 0; m < 4; m++)
                out[base + rg*4 + m] = 1.f / (1.f + __expf(-part[m]));
        }
    }
}

// ---------------------------------------------------------------------------
extern "C" void kernel_launch(void* const* d_in, const int* in_sizes, int n_in,
                              void* d_out, int out_size)
{
    (void)in_sizes; (void)n_in; (void)out_size;
    const float* nf   = (const float*)d_in[0];
    const float* frag = (const float*)d_in[1];
    const float* Wi   = (const float*)d_in[2];
    const float* bi   = (const float*)d_in[3];
    const float* U    = (const float*)d_in[4];
    const float* V    = (const float*)d_in[5];
    const float* q    = (const float*)d_in[6];
    const float* gW   = (const float*)d_in[7];
    const float* gb   = (const float*)d_in[8];
    float* out = (float*)d_out;

    const int SM_GEMM = (64*68 + 64*132 + 128 + 16) * 4;                  // 51776
    const int SM_XPI  = (64*132 + 32*134 + 64*34 + JD*KD + 64*41) * 4;    // 75264
    const int SM_HG   = (64*41 + JD*KD + 64*34 + KD*132 + JD + JD + 256)*4; // 42560
    const int SM_FIN  = (64*132 + 32*134 + 64*34 + KD*KD) * 4;            // 63744

    cudaFuncSetAttribute((const void*)k_in_gemm, cudaFuncAttributeMaxDynamicSharedMemorySize, SM_GEMM);
    cudaFuncSetAttribute((const void*)k_xp_I,    cudaFuncAttributeMaxDynamicSharedMemorySize, SM_XPI);
    cudaFuncSetAttribute((const void*)k_h_gate,  cudaFuncAttributeMaxDynamicSharedMemorySize, SM_HG);
    cudaFuncSetAttribute((const void*)k_final,   cudaFuncAttributeMaxDynamicSharedMemorySize, SM_FIN);

    k_zero<<<10, TPB>>>();
    k_in_gemm<<<NTOT/64, TPB, SM_GEMM>>>(nf, Wi, bi, 0);
    k_in_gemm<<<NB*JD/64, TPB, SM_GEMM>>>(frag, Wi, bi, 1);
    k_finalize<<<1, 32>>>();
    k_yp<<<NB*5, TPB>>>(V, q);
    k_G<<<NB, TPB>>>();

    for (int l = 0; l < 2; l++) {
        k_xp_I  <<<NTOT/64,  TPB, SM_XPI>>>(U, l);
        k_sumexp<<<NTOT/128, TPB>>>(l);
        k_h_gate<<<NTOT/64,  TPB, SM_HG>>>(V, gW, gb, l);
    }
    k_final<<<NTOT/64, TPB, SM_FIN>>>(U, out);
}

// round 14
// speedup vs baseline: 1.9114x; 1.0092x over previous
#include <cuda_runtime.h>
#include <math.h>

#define NB    32
#define NPG   4096
#define NTOT  (NB*NPG)      // 131072 nodes
#define FIN   64
#define CD    128
#define KD    32
#define JD    40
#define EPSV  1e-5f
#define TPB   256

typedef unsigned long long u64;

__device__ __forceinline__ u64 PK2(float lo, float hi) {
    u64 r; asm("mov.b64 %0, {%1,%2};" : "=l"(r) : "f"(lo), "f"(hi)); return r;
}
__device__ __forceinline__ u64 SPLAT(float v) {
    u64 r; asm("mov.b64 %0, {%1,%1};" : "=l"(r) : "f"(v)); return r;
}
__device__ __forceinline__ void FMA2(u64& d, u64 a, u64 b) {
    asm("fma.rn.f32x2 %0, %1, %2, %0;" : "+l"(d) : "l"(a), "l"(b));
}
__device__ __forceinline__ float2 UPK(u64 v) {
    float lo, hi; asm("mov.b64 {%0,%1}, %2;" : "=f"(lo), "=f"(hi) : "l"(v));
    return make_float2(lo, hi);
}

// ---------------- scratch (device globals: no allocs allowed) ----------------
__device__ float  g_t [NTOT*CD];     // t = nf@W^T+b, later in-place gated x
__device__ float  g_P [NTOT*JD];     // raw I, then exp(I-M) in place per layer
__device__ float  g_ty[NB*JD*CD];    // frag pre-LN
__device__ float  g_yp[NB*JD*KD];    // y_p (raw)
__device__ float  g_G [NB*KD*KD];    // y_p^T y_p per graph
__device__ double g_red[4];          // node sum/sumsq, frag sum/sumsq
__device__ float  g_ln[4];           // node mean,rstd ; frag mean,rstd
__device__ float  g_M[2*NB*JD];      // per-layer column max (I>=0 so init 0 ok)
__device__ float  g_S[2*NB*JD];      // per-layer column sum-exp

// ---------------------------------------------------------------------------
__global__ void k_zero() {
    int t = blockIdx.x*blockDim.x + threadIdx.x;
    if (t < 4) g_red[t] = 0.0;
    if (t < 2*NB*JD) { g_M[t] = 0.f; g_S[t] = 0.f; }
}

// out[row][c] = sum_d in[row][d]*W[c][d] + b[c]; 64 rows x 128 cols per block.
// f32x2: strided column pairs (2cg + 32u) -> conflict-free LDS64 on Ws.
__global__ void k_in_gemm(const float* __restrict__ in, const float* __restrict__ W,
                          const float* __restrict__ bias, int which)
{
    extern __shared__ float sm[];
    float* As = sm;              // [64][68]  input tile
    float* Ws = As + 64*68;      // [64][132] W^T, k-major
    float* bs = Ws + 64*132;     // [128]
    float* r1 = bs + 128;        // [8]
    float* r2 = r1 + 8;          // [8]
    float* outg = which ? g_ty : g_t;
    const int slot = which * 2;
    const int t = threadIdx.x;
    const int base = blockIdx.x * 64;

    #pragma unroll
    for (int i = 0; i < 4; i++) {                 // A tile: 64x64 floats
        int f = t + i*TPB;
        int r = f >> 4, cq = f & 15;
        float4 v = reinterpret_cast<const float4*>(in)[(base + r)*(FIN/4) + cq];
        *reinterpret_cast<float4*>(&As[r*68 + cq*4]) = v;
    }
    #pragma unroll
    for (int i = 0; i < 8; i++) {                 // W [128][64] -> Ws[k][c]
        int f = t + i*TPB;
        int c = f >> 4, kq = f & 15;
        float4 v = reinterpret_cast<const float4*>(W)[c*(FIN/4) + kq];
        Ws[(kq*4+0)*132 + c] = v.x;
        Ws[(kq*4+1)*132 + c] = v.y;
        Ws[(kq*4+2)*132 + c] = v.z;
        Ws[(kq*4+3)*132 + c] = v.w;
    }
    if (t < CD) bs[t] = bias[t];
    __syncthreads();

    const int rg = t >> 4, cg = t & 15;           // 4 rows x 4 strided pairs
    u64 acc[4][4] = {};

    #pragma unroll 4
    for (int k = 0; k < 64; k++) {
        u64 av[4], bv[4];
        #pragma unroll
        for (int m = 0; m < 4; m++) av[m] = SPLAT(As[(rg*4+m)*68 + k]);
        #pragma unroll
        for (int u = 0; u < 4; u++)
            bv[u] = *reinterpret_cast<const u64*>(&Ws[k*132 + cg*2 + 32*u]);
        #pragma unroll
        for (int m = 0; m < 4; m++)
            #pragma unroll
            for (int u = 0; u < 4; u++) FMA2(acc[m][u], av[m], bv[u]);
    }

    float s1 = 0.f, s2 = 0.f;
    #pragma unroll
    for (int m = 0; m < 4; m++) {
        int row = base + rg*4 + m;
        #pragma unroll
        for (int u = 0; u < 4; u++) {
            float2 p = UPK(acc[m][u]);
            float o0 = p.x + bs[cg*2 + 32*u];
            float o1 = p.y + bs[cg*2 + 32*u + 1];
            s1 += o0 + o1;
            s2 = fmaf(o0, o0, fmaf(o1, o1, s2));
            *reinterpret_cast<float2*>(&outg[row*CD + cg*2 + 32*u]) = make_float2(o0, o1);
        }
    }
    #pragma unroll
    for (int off = 16; off; off >>= 1) {
        s1 += __shfl_xor_sync(0xffffffffu, s1, off);
        s2 += __shfl_xor_sync(0xffffffffu, s2, off);
    }
    if ((t & 31) == 0) { r1[t>>5] = s1; r2[t>>5] = s2; }
    __syncthreads();
    if (t == 0) {
        float a = 0.f, b = 0.f;
        #pragma unroll
        for (int w = 0; w < 8; w++) { a += r1[w]; b += r2[w]; }
        atomicAdd(&g_red[slot],   (double)a);
        atomicAdd(&g_red[slot+1], (double)b);
    }
}

// One thread: fold double sums into float mean/rstd (FP64 confined here).
__global__ void k_finalize() {
    if (threadIdx.x == 0) {
        double ne = (double)NTOT * CD;
        double m  = g_red[0] / ne;
        double v  = g_red[1] / ne - m*m;
        g_ln[0] = (float)m;
        g_ln[1] = (float)(1.0 / sqrt(v + (double)EPSV));
        double nf = (double)NB * JD * CD;
        double mf = g_red[2] / nf;
        double vf = g_red[3] / nf - mf*mf;
        g_ln[2] = (float)mf;
        g_ln[3] = (float)(1.0 / sqrt(vf + (double)EPSV));
    }
}

// y_p = relu(q * relu(LN(ty) @ V)); grid NB*5, each block = 8 j rows of one graph.
__global__ void k_yp(const float* __restrict__ V, const float* __restrict__ q)
{
    __shared__ float ysn[8*132];
    __shared__ float Vs[CD*KD];
    __shared__ float qs[KD];
    const int t = threadIdx.x;
    const int b = blockIdx.x / 5, jg = blockIdx.x % 5;
    const float mf = g_ln[2], rf = g_ln[3];

    #pragma unroll
    for (int i = 0; i < 4; i++) {                  // 8 rows x 128 = 1024 floats
        int f = t + i*TPB;
        int r = f >> 7, c = f & 127;
        ysn[r*132 + c] = (g_ty[(b*JD + jg*8 + r)*CD + c] - mf) * rf;
    }
    #pragma unroll
    for (int i = 0; i < 16; i++) Vs[t + i*TPB] = V[t + i*TPB];
    if (t < KD) qs[t] = q[t];
    __syncthreads();

    const int j = t >> 5, k = t & 31;              // one output per thread
    float a0 = 0.f, a1 = 0.f, a2 = 0.f, a3 = 0.f;
    #pragma unroll
    for (int d = 0; d < CD; d += 4) {
        a0 = fmaf(ysn[j*132 + d    ], Vs[(d    )*KD + k], a0);
        a1 = fmaf(ysn[j*132 + d + 1], Vs[(d + 1)*KD + k], a1);
        a2 = fmaf(ysn[j*132 + d + 2], Vs[(d + 2)*KD + k], a2);
        a3 = fmaf(ysn[j*132 + d + 3], Vs[(d + 3)*KD + k], a3);
    }
    float acc = (a0 + a1) + (a2 + a3);
    g_yp[b*JD*KD + (jg*8 + j)*KD + k] = fmaxf(qs[k] * fmaxf(acc, 0.f), 0.f);
}

// G = y_p^T y_p per graph; grid NB  (launched late so ncu -s 5 captures k_xp_I)
__global__ void k_G()
{
    __shared__ float yps[JD*KD];
    const int t = threadIdx.x, b = blockIdx.x;
    for (int i = t; i < JD*KD; i += TPB) yps[i] = g_yp[b*JD*KD + i];
    __syncthreads();
    #pragma unroll
    for (int i = 0; i < 4; i++) {
        int o = t + i*TPB;
        int k1 = o >> 5, k2 = o & 31;
        float acc = 0.f;
        #pragma unroll
        for (int j = 0; j < JD; j++) acc = fmaf(yps[j*KD+k1], yps[j*KD+k2], acc);
        g_G[b*KD*KD + o] = acc;
    }
}

// 64 nodes/block: x_p = relu(x@U); I = x_p @ y_p^T; write I; atomicMax column max
__global__ void k_xp_I(const float* __restrict__ U, int layer)
{
    extern __shared__ float sm[];
    float* Xs  = sm;               // [64][132]
    float* Ust = Xs + 64*132;      // [32][134]  U transposed, k-major over c
    float* Xps = Ust + 32*134;     // [64][34]
    float* Yps = Xps + 64*34;      // [40][32]
    float* Is  = Yps + JD*KD;      // [64][41]
    const int t = threadIdx.x;
    const int b = blockIdx.x >> 6, tile = blockIdx.x & 63;
    const int base = b*NPG + tile*64;
    const float mean = layer == 0 ? g_ln[0] : 0.f;
    const float rstd = layer == 0 ? g_ln[1] : 1.f;

    #pragma unroll
    for (int i = 0; i < 8; i++) {
        int f = t + i*TPB;
        int r = f >> 5, cq = f & 31;
        float4 v = reinterpret_cast<const float4*>(g_t)[(base + r)*(CD/4) + cq];
        v.x = (v.x-mean)*rstd; v.y = (v.y-mean)*rstd;
        v.z = (v.z-mean)*rstd; v.w = (v.w-mean)*rstd;
        *reinterpret_cast<float4*>(&Xs[r*132 + cq*4]) = v;
    }
    #pragma unroll
    for (int i = 0; i < 16; i++) {                // U [128][32] -> Ust[k][c]
        int f = t + i*TPB;
        int c = f >> 5, k = f & 31;
        Ust[k*134 + c] = U[f];
    }
    for (int i = t; i < JD*KD; i += TPB) Yps[i] = g_yp[b*JD*KD + i];
    __syncthreads();

    const int rg = t >> 4, cg = t & 15;
    { // phase 1: Xp = relu(X@U), thread = 4 rows x 2 cols, k-packed over c
        u64 acc[4][2] = {};
        #pragma unroll 8
        for (int c2 = 0; c2 < 64; c2++) {
            u64 a2[4], b2[2];
            #pragma unroll
            for (int m = 0; m < 4; m++)
                a2[m] = *reinterpret_cast<const u64*>(&Xs[(rg*4+m)*132 + 2*c2]);
            #pragma unroll
            for (int d = 0; d < 2; d++)
                b2[d] = *reinterpret_cast<const u64*>(&Ust[(cg*2+d)*134 + 2*c2]);
            #pragma unroll
            for (int m = 0; m < 4; m++) {
                FMA2(acc[m][0], a2[m], b2[0]);
                FMA2(acc[m][1], a2[m], b2[1]);
            }
        }
        #pragma unroll
        for (int m = 0; m < 4; m++) {
            float2 p0 = UPK(acc[m][0]), p1 = UPK(acc[m][1]);
            float v0 = fmaxf(p0.x + p0.y, 0.f);
            float v1 = fmaxf(p1.x + p1.y, 0.f);
            *reinterpret_cast<u64*>(&Xps[(rg*4+m)*34 + cg*2]) = PK2(v0, v1);
        }
    }
    __syncthreads();

    { // phase 2: I rows; thread = (node r, 10 j's), pair-packed dot
        const int r = t & 63, js = t >> 6;
        u64 xp2[16];
        #pragma unroll
        for (int p = 0; p < 16; p++)
            xp2[p] = *reinterpret_cast<const u64*>(&Xps[r*34 + 2*p]);
        #pragma unroll
        for (int jj = 0; jj < 10; jj++) {
            int j = js*10 + jj;
            u64 a = 0;
            #pragma unroll
            for (int p = 0; p < 16; p++)
                FMA2(a, xp2[p], *reinterpret_cast<const u64*>(&Yps[j*32 + 2*p]));
            float2 pr = UPK(a);
            Is[r*41 + j] = pr.x + pr.y;
        }
    }
    __syncthreads();

    float* gP = g_P + (long)base * JD;
    for (int o = t; o < 64*JD; o += TPB) gP[o] = Is[(o/JD)*41 + (o%JD)];
    if (t < JD) {
        float m = 0.f;
        for (int r = 0; r < 64; r++) m = fmaxf(m, Is[r*41 + t]);
        atomicMax((int*)(g_M + layer*NB*JD + b*JD + t), __float_as_int(m));
    }
}

// E = exp(I-M) written back in place (single exp pass); accumulate column sums
__global__ void k_sumexp(int layer)
{
    __shared__ float Ms[JD], sj[JD];
    const int t = threadIdx.x;
    const int b = blockIdx.x >> 5, chunk = blockIdx.x & 31;    // 128 nodes/block
    const long base = ((long)b*NPG + chunk*128) * JD;
    if (t < JD) { Ms[t] = g_M[layer*NB*JD + b*JD + t]; sj[t] = 0.f; }
    __syncthreads();
    float loc[5] = {0,0,0,0,0};
    #pragma unroll
    for (int i = 0; i < 20; i++) {                // 128*40 / 256
        int o = t + i*TPB;
        int j = o % JD;
        float e = __expf(g_P[base + o] - Ms[j]);
        g_P[base + o] = e;
        loc[j >> 3] += e;
    }
    const int jc = t & 7;
    #pragma unroll
    for (int i = 0; i < 5; i++) atomicAdd(&sj[i*8 + jc], loc[i]);
    __syncthreads();
    if (t < JD) atomicAdd(&g_S[layer*NB*JD + b*JD + t], sj[t]);
}

// E preloaded from g_P; H = relu(E @ (y_p/S)); hC = H@V^T; gate; x update
__global__ void k_h_gate(const float* __restrict__ V, const float* __restrict__ gW,
                         const float* __restrict__ gb, int layer)
{
    extern __shared__ float sm[];
    float* Es   = sm;                 // [64][41]  E (already exponentiated)
    float* Yps2 = Es + 64*41;         // [40][32]  y_p/S
    float* Hs   = Yps2 + JD*KD;       // [64][34]
    float* Vst  = Hs + 64*34;         // [32][132] (k-major V^T)
    float* invS = Vst + KD*132;       // [40]
    float* gws  = invS + JD;          // [256]
    const int t = threadIdx.x;
    const int b = blockIdx.x >> 6, tile = blockIdx.x & 63;
    const int base = b*NPG + tile*64;
    const float mean = layer == 0 ? g_ln[0] : 0.f;
    const float rstd = layer == 0 ? g_ln[1] : 1.f;
    const float gb0 = gb[0];

    if (t < JD) invS[t] = 1.f / g_S[layer*NB*JD + b*JD + t];
    gws[t] = gW[t];
    __syncthreads();
    for (int i = t; i < JD*KD; i += TPB) Yps2[i] = g_yp[b*JD*KD + i] * invS[i >> 5];
    #pragma unroll
    for (int i = 0; i < 4; i++) {                  // V [128][32] -> Vst[k][c]
        int f = t + i*TPB;
        int c = f >> 3, kq = f & 7;
        float4 v = reinterpret_cast<const float4*>(V)[c*(KD/4) + kq];
        Vst[(kq*4+0)*132 + c] = v.x;
        Vst[(kq*4+1)*132 + c] = v.y;
        Vst[(kq*4+2)*132 + c] = v.z;
        Vst[(kq*4+3)*132 + c] = v.w;
    }
    for (int o = t; o < 64*JD; o += TPB) {
        int r = o / JD, j = o - r*JD;
        Es[r*41 + j] = g_P[(long)base*JD + o];
    }
    __syncthreads();

    const int rg = t >> 4, cg = t & 15;
    { // phase 1: H[64][32] = relu(E @ Yps2), col-pair f32x2
        u64 acc[4] = {};
        #pragma unroll 8
        for (int j = 0; j < JD; j++) {
            u64 b2 = *reinterpret_cast<const u64*>(&Yps2[j*32 + cg*2]);
            #pragma unroll
            for (int m = 0; m < 4; m++)
                FMA2(acc[m], SPLAT(Es[(rg*4+m)*41 + j]), b2);
        }
        #pragma unroll
        for (int m = 0; m < 4; m++) {
            float2 p = UPK(acc[m]);
            *reinterpret_cast<u64*>(&Hs[(rg*4+m)*34 + cg*2]) =
                PK2(fmaxf(p.x, 0.f), fmaxf(p.y, 0.f));
        }
    }
    __syncthreads();

    // phase 2: hC[64][128], strided col pairs (2cg+32u); then gate + update
    u64 hcp[4][4] = {};
    #pragma unroll 4
    for (int k = 0; k < KD; k++) {
        u64 av[4], bv[4];
        #pragma unroll
        for (int m = 0; m < 4; m++) av[m] = SPLAT(Hs[(rg*4+m)*34 + k]);
        #pragma unroll
        for (int u = 0; u < 4; u++)
            bv[u] = *reinterpret_cast<const u64*>(&Vst[k*132 + cg*2 + 32*u]);
        #pragma unroll
        for (int m = 0; m < 4; m++)
            #pragma unroll
            for (int u = 0; u < 4; u++) FMA2(hcp[m][u], av[m], bv[u]);
    }

    float gp[4], xvf[4][8], hcf[4][8];
    #pragma unroll
    for (int m = 0; m < 4; m++) {
        int row = base + rg*4 + m;
        float p = 0.f;
        #pragma unroll
        for (int u = 0; u < 4; u++) {
            float2 hv = UPK(hcp[m][u]);
            float2 xr = *reinterpret_cast<const float2*>(&g_t[row*CD + cg*2 + 32*u]);
            float x0 = (xr.x - mean) * rstd, x1 = (xr.y - mean) * rstd;
            hcf[m][2*u] = hv.x; hcf[m][2*u+1] = hv.y;
            xvf[m][2*u] = x0;   xvf[m][2*u+1] = x1;
            p = fmaf(x0, gws[cg*2 + 32*u],      p);
            p = fmaf(x1, gws[cg*2 + 32*u + 1],  p);
            p = fmaf(hv.x, gws[CD + cg*2 + 32*u],     p);
            p = fmaf(hv.y, gws[CD + cg*2 + 32*u + 1], p);
        }
        gp[m] = p;
    }
    #pragma unroll
    for (int off = 8; off; off >>= 1)
        #pragma unroll
        for (int m = 0; m < 4; m++)
            gp[m] += __shfl_xor_sync(0xffffffffu, gp[m], off);
    #pragma unroll
    for (int m = 0; m < 4; m++) {
        float z = 1.f / (1.f + __expf(-(gp[m] + gb0)));
        int row = base + rg*4 + m;
        #pragma unroll
        for (int u = 0; u < 4; u++) {
            float o0 = fmaf(z, hcf[m][2*u]   - xvf[m][2*u],   xvf[m][2*u]);
            float o1 = fmaf(z, hcf[m][2*u+1] - xvf[m][2*u+1], xvf[m][2*u+1]);
            *reinterpret_cast<float2*>(&g_t[row*CD + cg*2 + 32*u]) = make_float2(o0, o1);
        }
    }
}

// x_p = relu(x@U); out = sigmoid(x_p . (x_p @ G))
__global__ void k_final(const float* __restrict__ U, float* __restrict__ out)
{
    extern __shared__ float sm[];
    float* Xs  = sm;               // [64][132]
    float* Ust = Xs + 64*132;      // [32][134]
    float* Xps = Ust + 32*134;     // [64][34]
    float* Gs  = Xps + 64*34;      // [32][32]
    const int t = threadIdx.x;
    const int b = blockIdx.x >> 6, tile = blockIdx.x & 63;
    const int base = b*NPG + tile*64;

    #pragma unroll
    for (int i = 0; i < 8; i++) {
        int f = t + i*TPB;
        int r = f >> 5, cq = f & 31;
        float4 v = reinterpret_cast<const float4*>(g_t)[(base + r)*(CD/4) + cq];
        *reinterpret_cast<float4*>(&Xs[r*132 + cq*4]) = v;
    }
    #pragma unroll
    for (int i = 0; i < 16; i++) {
        int f = t + i*TPB;
        int c = f >> 5, k = f & 31;
        Ust[k*134 + c] = U[f];
    }
    for (int i = t; i < KD*KD; i += TPB) Gs[i] = g_G[b*KD*KD + i];
    __syncthreads();

    const int rg = t >> 4, cg = t & 15;
    { // Xp = relu(X@U), k-packed over c
        u64 acc[4][2] = {};
        #pragma unroll 8
        for (int c2 = 0; c2 < 64; c2++) {
            u64 a2[4], b2[2];
            #pragma unroll
            for (int m = 0; m < 4; m++)
                a2[m] = *reinterpret_cast<const u64*>(&Xs[(rg*4+m)*132 + 2*c2]);
            #pragma unroll
            for (int d = 0; d < 2; d++)
                b2[d] = *reinterpret_cast<const u64*>(&Ust[(cg*2+d)*134 + 2*c2]);
            #pragma unroll
            for (int m = 0; m < 4; m++) {
                FMA2(acc[m][0], a2[m], b2[0]);
                FMA2(acc[m][1], a2[m], b2[1]);
            }
        }
        #pragma unroll
        for (int m = 0; m < 4; m++) {
            float2 p0 = UPK(acc[m][0]), p1 = UPK(acc[m][1]);
            float v0 = fmaxf(p0.x + p0.y, 0.f);
            float v1 = fmaxf(p1.x + p1.y, 0.f);
            *reinterpret_cast<u64*>(&Xps[(rg*4+m)*34 + cg*2]) = PK2(v0, v1);
        }
    }
    __syncthreads();
    { // tvec = Xp@G (col pairs), dot with Xp, reduce over 16 lanes
        u64 acc[4] = {};
        #pragma unroll
        for (int k = 0; k < KD; k++) {
            u64 b2 = *reinterpret_cast<const u64*>(&Gs[k*32 + cg*2]);
            #pragma unroll
            for (int m = 0; m < 4; m++)
                FMA2(acc[m], SPLAT(Xps[(rg*4+m)*34 + k]), b2);
        }
        float part[4];
        #pragma unroll
        for (int m = 0; m < 4; m++) {
            float2 p = UPK(acc[m]);
            part[m] = p.x * Xps[(rg*4+m)*34 + cg*2]
                    + p.y * Xps[(rg*4+m)*34 + cg*2 + 1];
        }
        #pragma unroll
        for (int off = 8; off; off >>= 1)
            #pragma unroll
            for (int m = 0; m < 4; m++)
                part[m] += __shfl_xor_sync(0xffffffffu, part[m], off);
        if (cg == 0) {
            #pragma unroll
            for (int m = 0; m < 4; m++)
                out[base + rg*4 + m] = 1.f / (1.f + __expf(-part[m]));
        }
    }
}

// ---------------------------------------------------------------------------
extern "C" void kernel_launch(void* const* d_in, const int* in_sizes, int n_in,
                              void* d_out, int out_size)
{
    (void)in_sizes; (void)n_in; (void)out_size;
    const float* nf   = (const float*)d_in[0];
    const float* frag = (const float*)d_in[1];
    const float* Wi   = (const float*)d_in[2];
    const float* bi   = (const float*)d_in[3];
    const float* U    = (const float*)d_in[4];
    const float* V    = (const float*)d_in[5];
    const float* q    = (const float*)d_in[6];
    const float* gW   = (const float*)d_in[7];
    const float* gb   = (const float*)d_in[8];
    float* out = (float*)d_out;

    const int SM_GEMM = (64*68 + 64*132 + 128 + 16) * 4;                  // 51776
    const int SM_XPI  = (64*132 + 32*134 + 64*34 + JD*KD + 64*41) * 4;    // 75264
    const int SM_HG   = (64*41 + JD*KD + 64*34 + KD*132 + JD + 256) * 4;  // 42400
    const int SM_FIN  = (64*132 + 32*134 + 64*34 + KD*KD) * 4;            // 63744

    cudaFuncSetAttribute((const void*)k_in_gemm, cudaFuncAttributeMaxDynamicSharedMemorySize, SM_GEMM);
    cudaFuncSetAttribute((const void*)k_xp_I,    cudaFuncAttributeMaxDynamicSharedMemorySize, SM_XPI);
    cudaFuncSetAttribute((const void*)k_h_gate,  cudaFuncAttributeMaxDynamicSharedMemorySize, SM_HG);
    cudaFuncSetAttribute((const void*)k_final,   cudaFuncAttributeMaxDynamicSharedMemorySize, SM_FIN);

    k_zero<<<10, TPB>>>();
    k_in_gemm<<<NTOT/64, TPB, SM_GEMM>>>(nf, Wi, bi, 0);
    k_in_gemm<<<NB*JD/64, TPB, SM_GEMM>>>(frag, Wi, bi, 1);
    k_finalize<<<1, 32>>>();
    k_yp<<<NB*5, TPB>>>(V, q);

    for (int l = 0; l < 2; l++) {
        k_xp_I  <<<NTOT/64,  TPB, SM_XPI>>>(U, l);     // 6th launch (l=0): ncu target
        k_sumexp<<<NTOT/128, TPB>>>(l);
        k_h_gate<<<NTOT/64,  TPB, SM_HG>>>(V, gW, gb, l);
    }
    k_G<<<NB, TPB>>>();                                 // G only needed by k_final
    k_final<<<NTOT/64, TPB, SM_FIN>>>(U, out);
}